// round 3
// baseline (speedup 1.0000x reference)
#include <cuda_runtime.h>
#include <math.h>

#define N_SEQ 4096
#define M_SEQ 1024
#define DIMC  512
#define INNER 512
#define HEADS 8
#define DH    64
#define GROUPS 8

typedef unsigned long long ull;

// ---------------- f32x2 packed-math helpers (SASS FFMA2 path) -----------------
__device__ __forceinline__ ull splat2(float x) {
    ull r;
    asm("mov.b64 %0, {%1, %1};" : "=l"(r) : "r"(__float_as_uint(x)));
    return r;
}
__device__ __forceinline__ ull fma2(ull a, ull b, ull c) {
    ull d;
    asm("fma.rn.f32x2 %0, %1, %2, %3;" : "=l"(d) : "l"(a), "l"(b), "l"(c));
    return d;
}
__device__ __forceinline__ ull mul2(ull a, ull b) {
    ull d;
    asm("mul.rn.f32x2 %0, %1, %2;" : "=l"(d) : "l"(a), "l"(b));
    return d;
}
__device__ __forceinline__ void unpack2(ull v, float& lo, float& hi) {
    unsigned int l, h;
    asm("mov.b64 {%0, %1}, %2;" : "=r"(l), "=r"(h) : "l"(v));
    lo = __uint_as_float(l); hi = __uint_as_float(h);
}

// ---------------- scratch (static device globals; no allocation) ----------------
__device__ float g_q[INNER * N_SEQ];          // q[c][i]               8 MB
__device__ float g_pos[GROUPS * M_SEQ];       // sample positions      32 KB
__device__ float g_kvT[2 * M_SEQ * INNER];    // kv[s][t][ch]          4 MB
__device__ float g_k[2 * INNER * M_SEQ];      // k[s][c][t]            4 MB
__device__ float g_v[2 * INNER * M_SEQ];      // v[s][c][t]            4 MB
__device__ float g_att[2 * INNER * N_SEQ];    // attn out [s][c][i]   16 MB

// ================= Kernel 1: grouped 1x1 q projection ==========================
__global__ __launch_bounds__(256) void qproj_kernel(
    const float* __restrict__ x, const float* __restrict__ px,
    const float* __restrict__ Wq)
{
    __shared__ float As[16][68];   // As[k][c]
    __shared__ float Bs[16][68];   // Bs[k][i]
    const int g  = blockIdx.y;
    const int i0 = blockIdx.x * 64;
    const int c0 = g * 64;
    const float* src  = (g < 4) ? px : x;
    const int   base  = (g & 3) * 128;
    const int tid = threadIdx.x;
    const int tx = tid & 15, ty = tid >> 4;

    ull acc2[4][2];
    #pragma unroll
    for (int a = 0; a < 4; a++) { acc2[a][0] = 0ULL; acc2[a][1] = 0ULL; }

    for (int k0 = 0; k0 < 128; k0 += 16) {
        {
            int c = tid >> 2, k = (tid & 3) * 4;
            float4 w = *(const float4*)&Wq[(c0 + c) * 128 + k0 + k];
            As[k+0][c] = w.x; As[k+1][c] = w.y; As[k+2][c] = w.z; As[k+3][c] = w.w;
        }
        {
            int i = tid >> 2, k = (tid & 3) * 4;
            float4 b4 = *(const float4*)&src[(i0 + i) * DIMC + base + k0 + k];
            Bs[k+0][i] = b4.x; Bs[k+1][i] = b4.y; Bs[k+2][i] = b4.z; Bs[k+3][i] = b4.w;
        }
        __syncthreads();
        #pragma unroll
        for (int kk = 0; kk < 16; kk++) {
            ull b0 = *(const ull*)&Bs[kk][tx*4];
            ull b1 = *(const ull*)&Bs[kk][tx*4+2];
            #pragma unroll
            for (int u = 0; u < 4; u++) {
                ull av = splat2(As[kk][ty*4 + u]);
                acc2[u][0] = fma2(av, b0, acc2[u][0]);
                acc2[u][1] = fma2(av, b1, acc2[u][1]);
            }
        }
        __syncthreads();
    }
    #pragma unroll
    for (int ai = 0; ai < 4; ai++) {
        float lo, hi;
        unpack2(acc2[ai][0], lo, hi);
        g_q[(c0 + ty*4 + ai) * N_SEQ + i0 + tx*4 + 0] = lo;
        g_q[(c0 + ty*4 + ai) * N_SEQ + i0 + tx*4 + 1] = hi;
        unpack2(acc2[ai][1], lo, hi);
        g_q[(c0 + ty*4 + ai) * N_SEQ + i0 + tx*4 + 2] = lo;
        g_q[(c0 + ty*4 + ai) * N_SEQ + i0 + tx*4 + 3] = hi;
    }
}

// ================= Kernel 2: offset network ====================================
__global__ __launch_bounds__(128) void offset_kernel(
    const float* __restrict__ Wdw, const float* __restrict__ bdw,
    const float* __restrict__ Wp)
{
    const int g = blockIdx.y;
    const int t = blockIdx.x * 128 + threadIdx.x;
    const float* qg = &g_q[g * 64 * N_SEQ];
    const int pbase = 4 * t - 1;
    float s = 0.f;
    for (int c = 0; c < 64; c++) {
        float hv = bdw[c];
        const float* qr = &qg[c * N_SEQ];
        #pragma unroll
        for (int k = 0; k < 6; k++) {
            int p = pbase + k;
            if (p >= 0 && p < N_SEQ) hv += Wdw[c * 6 + k] * qr[p];
        }
        hv = 0.5f * hv * (1.f + erff(hv * 0.7071067811865476f));  // exact gelu
        s += Wp[c] * hv;
    }
    float off = tanhf(s) * 4.0f;
    float vg  = 2.0f * ((float)t + off) / 1023.0f - 1.0f;
    float pos = ((vg + 1.0f) * (float)N_SEQ - 1.0f) * 0.5f;
    g_pos[g * M_SEQ + t] = pos;
}

// ================= Kernel 3: 1-D bilinear grid sample ==========================
__global__ __launch_bounds__(256) void gridsample_kernel(
    const float* __restrict__ x, const float* __restrict__ px)
{
    const int tid = blockIdx.x * 256 + threadIdx.x;
    const int c    = tid & 63;
    const int unit = tid >> 6;
    const int t  = unit & (M_SEQ - 1);
    const int sg = unit >> 10;
    const int g  = sg & 7;
    const int s  = sg >> 3;
    const float* src = (s == 0) ? px : x;
    const float pos = g_pos[g * M_SEQ + t];
    const float x0 = floorf(pos);
    const float w1 = pos - x0;
    const int p0 = (int)x0;
    const int ch = g * 64 + c;
    float v = 0.f;
    if (p0 >= 0 && p0 < N_SEQ)           v += (1.f - w1) * src[p0 * DIMC + ch];
    if (p0 + 1 >= 0 && p0 + 1 < N_SEQ)   v += w1 * src[(p0 + 1) * DIMC + ch];
    g_kvT[(s * M_SEQ + t) * INNER + ch] = v;
}

// ================= Kernel 4: grouped 1x1 k/v projection ========================
__global__ __launch_bounds__(256) void kvproj_kernel(
    const float* __restrict__ W, int which)
{
    __shared__ float As[16][68];
    __shared__ float Bs[16][68];
    const int g  = blockIdx.y;
    const int s  = blockIdx.z;
    const int t0 = blockIdx.x * 64;
    const int c0 = g * 64;
    const int tid = threadIdx.x;
    const int tx = tid & 15, ty = tid >> 4;
    const float* kvb = &g_kvT[s * M_SEQ * INNER];
    float* out = (which ? g_v : g_k) + s * INNER * M_SEQ;

    ull acc2[4][2];
    #pragma unroll
    for (int a = 0; a < 4; a++) { acc2[a][0] = 0ULL; acc2[a][1] = 0ULL; }

    for (int k0 = 0; k0 < 64; k0 += 16) {
        {
            int c = tid >> 2, k = (tid & 3) * 4;
            float4 w = *(const float4*)&W[(c0 + c) * 64 + k0 + k];
            As[k+0][c] = w.x; As[k+1][c] = w.y; As[k+2][c] = w.z; As[k+3][c] = w.w;
        }
        {
            int t = tid >> 2, k = (tid & 3) * 4;
            float4 b4 = *(const float4*)&kvb[(t0 + t) * INNER + c0 + k0 + k];
            Bs[k+0][t] = b4.x; Bs[k+1][t] = b4.y; Bs[k+2][t] = b4.z; Bs[k+3][t] = b4.w;
        }
        __syncthreads();
        #pragma unroll
        for (int kk = 0; kk < 16; kk++) {
            ull b0 = *(const ull*)&Bs[kk][tx*4];
            ull b1 = *(const ull*)&Bs[kk][tx*4+2];
            #pragma unroll
            for (int u = 0; u < 4; u++) {
                ull av = splat2(As[kk][ty*4 + u]);
                acc2[u][0] = fma2(av, b0, acc2[u][0]);
                acc2[u][1] = fma2(av, b1, acc2[u][1]);
            }
        }
        __syncthreads();
    }
    #pragma unroll
    for (int ai = 0; ai < 4; ai++) {
        float lo, hi;
        unpack2(acc2[ai][0], lo, hi);
        out[(c0 + ty*4 + ai) * M_SEQ + t0 + tx*4 + 0] = lo;
        out[(c0 + ty*4 + ai) * M_SEQ + t0 + tx*4 + 1] = hi;
        unpack2(acc2[ai][1], lo, hi);
        out[(c0 + ty*4 + ai) * M_SEQ + t0 + tx*4 + 2] = lo;
        out[(c0 + ty*4 + ai) * M_SEQ + t0 + tx*4 + 3] = hi;
    }
}

// ================= Kernel 5: flash-style attention (FFMA2) =====================
// per (stream, head): Q (4096x64) x K (1024x64)^T -> softmax -> x V (1024x64)
// Layouts: QS[d][i], KS[d][j], VT[d][j], PS[q][j]  (all [64][66])
__global__ __launch_bounds__(128) void attn_kernel()
{
    __shared__ float QS[64][66];
    __shared__ float KS[64][66];
    __shared__ float VT[64][66];
    __shared__ float PS[64][66];
    const int i0 = blockIdx.x * 64;
    const int h  = blockIdx.y;
    const int s  = blockIdx.z;
    const int tid = threadIdx.x;
    const int tx = tid & 15, ty = tid >> 4;

    const float* qb = &g_q[h * 64 * N_SEQ];
    for (int idx = tid; idx < 4096; idx += 128) {
        int d = idx >> 6, i = idx & 63;
        QS[d][i] = qb[d * N_SEQ + i0 + i] * 0.125f;
    }
    const float* kb = &g_k[s * INNER * M_SEQ + h * 64 * M_SEQ];
    const float* vb = &g_v[s * INNER * M_SEQ + h * 64 * M_SEQ];

    // output acc: pairs over j-parity; acc2[a][b] covers q-row (ty*8+a), d-col (tx*4+b)
    ull acc2[8][4];
    float m_i[8], l_i[8];
    #pragma unroll
    for (int a = 0; a < 8; a++) {
        m_i[a] = -1e30f; l_i[a] = 0.f;
        #pragma unroll
        for (int b = 0; b < 4; b++) acc2[a][b] = 0ULL;
    }

    for (int j0 = 0; j0 < M_SEQ; j0 += 64) {
        __syncthreads();   // previous tile's PV reads done
        for (int idx = tid; idx < 4096; idx += 128) {
            int d = idx >> 6, j = idx & 63;
            KS[d][j] = kb[d * M_SEQ + j0 + j];
            VT[d][j] = vb[d * M_SEQ + j0 + j];
        }
        __syncthreads();

        // ---- S = Q^T K tile: sv2 pairs over adjacent q rows ----
        ull sv2[4][4];
        #pragma unroll
        for (int u = 0; u < 4; u++)
            #pragma unroll
            for (int b = 0; b < 4; b++) sv2[u][b] = 0ULL;

        #pragma unroll 2
        for (int kk = 0; kk < 64; kk++) {
            ull qp[4];
            #pragma unroll
            for (int u = 0; u < 4; u++)
                qp[u] = *(const ull*)&QS[kk][ty * 8 + 2 * u];
            ull ks[4];
            #pragma unroll
            for (int b = 0; b < 4; b++)
                ks[b] = splat2(KS[kk][tx * 4 + b]);
            #pragma unroll
            for (int u = 0; u < 4; u++)
                #pragma unroll
                for (int b = 0; b < 4; b++)
                    sv2[u][b] = fma2(qp[u], ks[b], sv2[u][b]);
        }

        // ---- online softmax: unpack pairs, per-row reduce over 16 tx lanes ----
        #pragma unroll
        for (int u = 0; u < 4; u++) {
            float slo[4], shi[4];
            #pragma unroll
            for (int b = 0; b < 4; b++) unpack2(sv2[u][b], slo[b], shi[b]);
            #pragma unroll
            for (int r = 0; r < 2; r++) {
                const int a = 2 * u + r;
                float* sv = r ? shi : slo;
                float mx = fmaxf(fmaxf(sv[0], sv[1]), fmaxf(sv[2], sv[3]));
                #pragma unroll
                for (int o = 8; o >= 1; o >>= 1)
                    mx = fmaxf(mx, __shfl_xor_sync(0xffffffffu, mx, o));
                float mnew = fmaxf(m_i[a], mx);
                float corr = __expf(m_i[a] - mnew);
                float p0 = __expf(sv[0] - mnew);
                float p1 = __expf(sv[1] - mnew);
                float p2 = __expf(sv[2] - mnew);
                float p3 = __expf(sv[3] - mnew);
                *(float2*)&PS[ty * 8 + a][tx * 4]     = make_float2(p0, p1);
                *(float2*)&PS[ty * 8 + a][tx * 4 + 2] = make_float2(p2, p3);
                float rsum = p0 + p1 + p2 + p3;
                #pragma unroll
                for (int o = 8; o >= 1; o >>= 1)
                    rsum += __shfl_xor_sync(0xffffffffu, rsum, o);
                l_i[a] = l_i[a] * corr + rsum;
                m_i[a] = mnew;
                ull c2 = splat2(corr);
                #pragma unroll
                for (int b = 0; b < 4; b++) acc2[a][b] = mul2(acc2[a][b], c2);
            }
        }
        __syncwarp();   // PS rows are warp-private (ty decides rows) -> warp sync suffices

        // ---- acc += P x V : pairs over reduction (j parity), no splats ----
        #pragma unroll 2
        for (int j2 = 0; j2 < 32; j2++) {
            ull pp[8];
            #pragma unroll
            for (int a = 0; a < 8; a++)
                pp[a] = *(const ull*)&PS[ty * 8 + a][2 * j2];
            ull vv[4];
            #pragma unroll
            for (int b = 0; b < 4; b++)
                vv[b] = *(const ull*)&VT[tx * 4 + b][2 * j2];
            #pragma unroll
            for (int a = 0; a < 8; a++)
                #pragma unroll
                for (int b = 0; b < 4; b++)
                    acc2[a][b] = fma2(pp[a], vv[b], acc2[a][b]);
        }
    }
    __syncthreads();
    // epilogue: horizontal add of j-parity halves, normalize, stage through smem
    #pragma unroll
    for (int a = 0; a < 8; a++) {
        float inv = 1.f / l_i[a];
        #pragma unroll
        for (int b = 0; b < 4; b++) {
            float lo, hi;
            unpack2(acc2[a][b], lo, hi);
            KS[tx * 4 + b][ty * 8 + a] = (lo + hi) * inv;
        }
    }
    __syncthreads();
    float* ob = &g_att[s * INNER * N_SEQ + h * 64 * N_SEQ];
    for (int idx = tid; idx < 4096; idx += 128) {
        int d = idx >> 6, i = idx & 63;
        ob[d * N_SEQ + i0 + i] = KS[d][i];
    }
}

// ================= Kernel 6: stream-mean + Wo GEMM + bias ======================
__global__ __launch_bounds__(256) void outproj_kernel(
    const float* __restrict__ Wo, const float* __restrict__ bo,
    float* __restrict__ out)
{
    __shared__ float As[16][68];
    __shared__ float Bs[16][68];
    const int d0 = blockIdx.y * 64;
    const int i0 = blockIdx.x * 64;
    const int tid = threadIdx.x;
    const int tx = tid & 15, ty = tid >> 4;

    ull acc2[4][2];
    #pragma unroll
    for (int a = 0; a < 4; a++) { acc2[a][0] = 0ULL; acc2[a][1] = 0ULL; }

    for (int k0 = 0; k0 < 512; k0 += 16) {
        {
            int d = tid >> 2, k = (tid & 3) * 4;
            float4 w = *(const float4*)&Wo[(d0 + d) * INNER + k0 + k];
            As[k+0][d] = w.x; As[k+1][d] = w.y; As[k+2][d] = w.z; As[k+3][d] = w.w;
        }
        {
            int k = tid >> 4, i4 = (tid & 15) * 4;
            const float* a0 = &g_att[(k0 + k) * N_SEQ + i0 + i4];
            const float* a1 = a0 + INNER * N_SEQ;
            float4 v0 = *(const float4*)a0;
            float4 v1 = *(const float4*)a1;
            Bs[k][i4+0] = 0.5f * (v0.x + v1.x);
            Bs[k][i4+1] = 0.5f * (v0.y + v1.y);
            Bs[k][i4+2] = 0.5f * (v0.z + v1.z);
            Bs[k][i4+3] = 0.5f * (v0.w + v1.w);
        }
        __syncthreads();
        #pragma unroll
        for (int kk = 0; kk < 16; kk++) {
            ull b0 = *(const ull*)&Bs[kk][tx*4];
            ull b1 = *(const ull*)&Bs[kk][tx*4+2];
            #pragma unroll
            for (int u = 0; u < 4; u++) {
                ull av = splat2(As[kk][ty*4 + u]);
                acc2[u][0] = fma2(av, b0, acc2[u][0]);
                acc2[u][1] = fma2(av, b1, acc2[u][1]);
            }
        }
        __syncthreads();
    }
    #pragma unroll
    for (int ai = 0; ai < 4; ai++) {
        float bias = bo[d0 + ty*4 + ai];
        float lo, hi;
        unpack2(acc2[ai][0], lo, hi);
        out[(i0 + tx*4 + 0) * DIMC + d0 + ty*4 + ai] = lo + bias;
        out[(i0 + tx*4 + 1) * DIMC + d0 + ty*4 + ai] = hi + bias;
        unpack2(acc2[ai][1], lo, hi);
        out[(i0 + tx*4 + 2) * DIMC + d0 + ty*4 + ai] = lo + bias;
        out[(i0 + tx*4 + 3) * DIMC + d0 + ty*4 + ai] = hi + bias;
    }
}

// ================= launch ======================================================
extern "C" void kernel_launch(void* const* d_in, const int* in_sizes, int n_in,
                              void* d_out, int out_size)
{
    const float* x   = (const float*)d_in[0];
    const float* px  = (const float*)d_in[1];
    const float* Wq  = (const float*)d_in[2];
    const float* Wk  = (const float*)d_in[3];
    const float* Wv  = (const float*)d_in[4];
    const float* Wo  = (const float*)d_in[5];
    const float* bo  = (const float*)d_in[6];
    const float* Wdw = (const float*)d_in[7];
    const float* bdw = (const float*)d_in[8];
    const float* Wp  = (const float*)d_in[9];
    float* out = (float*)d_out;

    qproj_kernel<<<dim3(64, 8), 256>>>(x, px, Wq);
    offset_kernel<<<dim3(8, 8), 128>>>(Wdw, bdw, Wp);
    gridsample_kernel<<<4096, 256>>>(x, px);
    kvproj_kernel<<<dim3(16, 8, 2), 256>>>(Wk, 0);
    kvproj_kernel<<<dim3(16, 8, 2), 256>>>(Wv, 1);
    attn_kernel<<<dim3(64, HEADS, 2), 128>>>();
    outproj_kernel<<<dim3(64, 8), 256>>>(Wo, bo, out);
}

// round 5
// speedup vs baseline: 1.8219x; 1.8219x over previous
#include <cuda_runtime.h>
#include <cuda_bf16.h>
#include <math.h>

typedef unsigned int u32;
typedef unsigned long long u64;
typedef unsigned long long ull;

#define N_SEQ 4096
#define M_SEQ 1024
#define DIMC  512
#define INNER 512
#define HEADS 8
#define GROUPS 8

// ---------------- warp-MMA helpers (sm_80-class, no arch-suffix gating) --------
__device__ __forceinline__ u32 smem_u32(const void* p) {
    u32 a;
    asm("{ .reg .u64 t; cvta.to.shared.u64 t, %1; cvt.u32.u64 %0, t; }" : "=r"(a) : "l"(p));
    return a;
}
__device__ __forceinline__ float ex2f(float x) {
    float r; asm("ex2.approx.ftz.f32 %0, %1;" : "=f"(r) : "f"(x)); return r;
}
__device__ __forceinline__ void ldsm_x4(u32 addr, u32& r0, u32& r1, u32& r2, u32& r3) {
    asm volatile("ldmatrix.sync.aligned.m8n8.x4.shared.b16 {%0,%1,%2,%3}, [%4];"
        : "=r"(r0), "=r"(r1), "=r"(r2), "=r"(r3) : "r"(addr));
}
__device__ __forceinline__ void ldsm_x2(u32 addr, u32& r0, u32& r1) {
    asm volatile("ldmatrix.sync.aligned.m8n8.x2.shared.b16 {%0,%1}, [%2];"
        : "=r"(r0), "=r"(r1) : "r"(addr));
}
__device__ __forceinline__ void ldsm_x2_t(u32 addr, u32& r0, u32& r1) {
    asm volatile("ldmatrix.sync.aligned.m8n8.x2.trans.shared.b16 {%0,%1}, [%2];"
        : "=r"(r0), "=r"(r1) : "r"(addr));
}
__device__ __forceinline__ void mma16816(float* c, u32 a0, u32 a1, u32 a2, u32 a3,
                                         u32 b0, u32 b1) {
    asm volatile(
        "mma.sync.aligned.m16n8k16.row.col.f32.bf16.bf16.f32 "
        "{%0,%1,%2,%3}, {%4,%5,%6,%7}, {%8,%9}, {%0,%1,%2,%3};"
        : "+f"(c[0]), "+f"(c[1]), "+f"(c[2]), "+f"(c[3])
        : "r"(a0), "r"(a1), "r"(a2), "r"(a3), "r"(b0), "r"(b1));
}
__device__ __forceinline__ u32 pack_bf16(float a, float b) {
    return ((u32)__bfloat16_as_ushort(__float2bfloat16(b)) << 16) |
           (u32)__bfloat16_as_ushort(__float2bfloat16(a));
}
__device__ __forceinline__ float bfhi(float x) {
    return __bfloat162float(__float2bfloat16(x));
}

// ---------------- f32x2 helpers for scalar GEMMs -------------------------------
__device__ __forceinline__ ull splat2(float x) {
    ull r; asm("mov.b64 %0, {%1, %1};" : "=l"(r) : "r"(__float_as_uint(x))); return r;
}
__device__ __forceinline__ ull fma2(ull a, ull b, ull c) {
    ull d; asm("fma.rn.f32x2 %0, %1, %2, %3;" : "=l"(d) : "l"(a), "l"(b), "l"(c)); return d;
}
__device__ __forceinline__ void unpack2(ull v, float& lo, float& hi) {
    u32 l, h; asm("mov.b64 {%0, %1}, %2;" : "=r"(l), "=r"(h) : "l"(v));
    lo = __uint_as_float(l); hi = __uint_as_float(h);
}

// ---------------- scratch (static device globals) ------------------------------
__device__ float g_qT[N_SEQ * DIMC];                 // q[i][c]
__device__ float g_pos[GROUPS * M_SEQ];
__device__ float g_kvT[2 * M_SEQ * INNER];           // kv[s][t][ch]
__device__ __nv_bfloat16 g_khi[2 * M_SEQ * INNER];   // k hi  [s][t][c]
__device__ __nv_bfloat16 g_klo[2 * M_SEQ * INNER];   // k lo
__device__ __nv_bfloat16 g_vhi[2 * M_SEQ * INNER];   // v hi  [s][t][c]
__device__ __nv_bfloat16 g_vlo[2 * M_SEQ * INNER];   // v lo
__device__ float g_att[2 * INNER * N_SEQ];           // attn out [s][c][i]

// ================= Kernel 1: grouped 1x1 q projection ==========================
__global__ __launch_bounds__(256) void qproj_kernel(
    const float* __restrict__ x, const float* __restrict__ px,
    const float* __restrict__ Wq)
{
    __shared__ float As[16][68];
    __shared__ float Bs[16][68];
    const int g  = blockIdx.y;
    const int i0 = blockIdx.x * 64;
    const int c0 = g * 64;
    const float* src  = (g < 4) ? px : x;
    const int   base  = (g & 3) * 128;
    const int tid = threadIdx.x;
    const int tx = tid & 15, ty = tid >> 4;

    ull acc2[4][2];
    #pragma unroll
    for (int a = 0; a < 4; a++) { acc2[a][0] = 0ULL; acc2[a][1] = 0ULL; }

    for (int k0 = 0; k0 < 128; k0 += 16) {
        {
            int c = tid >> 2, k = (tid & 3) * 4;
            float4 w = *(const float4*)&Wq[(c0 + c) * 128 + k0 + k];
            As[k+0][c] = w.x; As[k+1][c] = w.y; As[k+2][c] = w.z; As[k+3][c] = w.w;
        }
        {
            int i = tid >> 2, k = (tid & 3) * 4;
            float4 b4 = *(const float4*)&src[(i0 + i) * DIMC + base + k0 + k];
            Bs[k+0][i] = b4.x; Bs[k+1][i] = b4.y; Bs[k+2][i] = b4.z; Bs[k+3][i] = b4.w;
        }
        __syncthreads();
        #pragma unroll
        for (int kk = 0; kk < 16; kk++) {
            ull b0 = *(const ull*)&Bs[kk][tx*4];
            ull b1 = *(const ull*)&Bs[kk][tx*4+2];
            #pragma unroll
            for (int u = 0; u < 4; u++) {
                ull av = splat2(As[kk][ty*4 + u]);
                acc2[u][0] = fma2(av, b0, acc2[u][0]);
                acc2[u][1] = fma2(av, b1, acc2[u][1]);
            }
        }
        __syncthreads();
    }
    #pragma unroll
    for (int ai = 0; ai < 4; ai++) {
        float v0, v1, v2, v3;
        unpack2(acc2[ai][0], v0, v1);
        unpack2(acc2[ai][1], v2, v3);
        const int c = c0 + ty*4 + ai;
        g_qT[(size_t)(i0 + tx*4 + 0) * DIMC + c] = v0;
        g_qT[(size_t)(i0 + tx*4 + 1) * DIMC + c] = v1;
        g_qT[(size_t)(i0 + tx*4 + 2) * DIMC + c] = v2;
        g_qT[(size_t)(i0 + tx*4 + 3) * DIMC + c] = v3;
    }
}

// ================= Kernel 2: offset network ====================================
__global__ __launch_bounds__(128) void offset_kernel(
    const float* __restrict__ Wdw, const float* __restrict__ bdw,
    const float* __restrict__ Wp)
{
    const int g = blockIdx.y;
    const int t = blockIdx.x * 128 + threadIdx.x;
    const int pbase = 4 * t - 1;
    float s = 0.f;
    for (int c = 0; c < 64; c++) {
        float hv = bdw[c];
        #pragma unroll
        for (int k = 0; k < 6; k++) {
            int p = pbase + k;
            if (p >= 0 && p < N_SEQ) hv += Wdw[c * 6 + k] * g_qT[(size_t)p * DIMC + g * 64 + c];
        }
        hv = 0.5f * hv * (1.f + erff(hv * 0.7071067811865476f));
        s += Wp[c] * hv;
    }
    float off = tanhf(s) * 4.0f;
    float vg  = 2.0f * ((float)t + off) / 1023.0f - 1.0f;
    float pos = ((vg + 1.0f) * (float)N_SEQ - 1.0f) * 0.5f;
    g_pos[g * M_SEQ + t] = pos;
}

// ================= Kernel 3: 1-D bilinear grid sample ==========================
__global__ __launch_bounds__(256) void gridsample_kernel(
    const float* __restrict__ x, const float* __restrict__ px)
{
    const int tid = blockIdx.x * 256 + threadIdx.x;
    const int c    = tid & 63;
    const int unit = tid >> 6;
    const int t  = unit & (M_SEQ - 1);
    const int sg = unit >> 10;
    const int g  = sg & 7;
    const int s  = sg >> 3;
    const float* src = (s == 0) ? px : x;
    const float pos = g_pos[g * M_SEQ + t];
    const float x0 = floorf(pos);
    const float w1 = pos - x0;
    const int p0 = (int)x0;
    const int ch = g * 64 + c;
    float v = 0.f;
    if (p0 >= 0 && p0 < N_SEQ)           v += (1.f - w1) * src[p0 * DIMC + ch];
    if (p0 + 1 >= 0 && p0 + 1 < N_SEQ)   v += w1 * src[(p0 + 1) * DIMC + ch];
    g_kvT[(size_t)(s * M_SEQ + t) * INNER + ch] = v;
}

// ================= Kernel 4: grouped 1x1 k/v projection (bf16-split [t][c]) ====
__global__ __launch_bounds__(256) void kvproj_kernel(
    const float* __restrict__ W, int which)   // 0 -> K, 1 -> V (both [s][t][c])
{
    __shared__ float As[16][68];
    __shared__ float Bs[16][68];
    const int g  = blockIdx.y;
    const int s  = blockIdx.z;
    const int t0 = blockIdx.x * 64;
    const int c0 = g * 64;
    const int tid = threadIdx.x;
    const int tx = tid & 15, ty = tid >> 4;
    const float* kvb = &g_kvT[(size_t)s * M_SEQ * INNER];
    __nv_bfloat16* ohi = (which == 0) ? g_khi : g_vhi;
    __nv_bfloat16* olo = (which == 0) ? g_klo : g_vlo;

    ull acc2[4][2];
    #pragma unroll
    for (int a = 0; a < 4; a++) { acc2[a][0] = 0ULL; acc2[a][1] = 0ULL; }

    for (int k0 = 0; k0 < 64; k0 += 16) {
        {
            int c = tid >> 2, k = (tid & 3) * 4;
            float4 w = *(const float4*)&W[(c0 + c) * 64 + k0 + k];
            As[k+0][c] = w.x; As[k+1][c] = w.y; As[k+2][c] = w.z; As[k+3][c] = w.w;
        }
        {
            int t = tid >> 2, k = (tid & 3) * 4;
            float4 b4 = *(const float4*)&kvb[(size_t)(t0 + t) * INNER + c0 + k0 + k];
            Bs[k+0][t] = b4.x; Bs[k+1][t] = b4.y; Bs[k+2][t] = b4.z; Bs[k+3][t] = b4.w;
        }
        __syncthreads();
        #pragma unroll
        for (int kk = 0; kk < 16; kk++) {
            ull b0 = *(const ull*)&Bs[kk][tx*4];
            ull b1 = *(const ull*)&Bs[kk][tx*4+2];
            #pragma unroll
            for (int u = 0; u < 4; u++) {
                ull av = splat2(As[kk][ty*4 + u]);
                acc2[u][0] = fma2(av, b0, acc2[u][0]);
                acc2[u][1] = fma2(av, b1, acc2[u][1]);
            }
        }
        __syncthreads();
    }
    #pragma unroll
    for (int ai = 0; ai < 4; ai++) {
        float v[4];
        unpack2(acc2[ai][0], v[0], v[1]);
        unpack2(acc2[ai][1], v[2], v[3]);
        const int c = c0 + ty*4 + ai;
        #pragma unroll
        for (int bi = 0; bi < 4; bi++) {
            const size_t idx = ((size_t)s * M_SEQ + t0 + tx*4 + bi) * INNER + c;
            __nv_bfloat16 hh = __float2bfloat16(v[bi]);
            ohi[idx] = hh;
            olo[idx] = __float2bfloat16(v[bi] - __bfloat162float(hh));
        }
    }
}

// ================= Kernel 5: warp-MMA flash attention ==========================
// CTA: 64 q-rows, 4 warps x 16 rows. Bc=64. bf16 3-term split both GEMMs.
#define SMSTRIDE 144          // 72 bf16 per row (pad 8 -> conflict-free ldmatrix)
#define O_KHI 0
#define O_KLO 9216
#define O_VHI 18432
#define O_VLO 27648
#define O_QHI 0               // Q staging aliases K region (used before loop only)
#define O_QLO 9216
#define SM_TOTAL 36864
#define QSCL 0.1803368801111204f   // 0.125 * log2(e)

__global__ __launch_bounds__(128) void attn_kernel()
{
    __shared__ __align__(16) char sm[SM_TOTAL];
    const int i0 = blockIdx.x * 64;
    const int h  = blockIdx.y;
    const int s  = blockIdx.z;
    const int tid = threadIdx.x;
    const int lane = tid & 31;
    const int wid = tid >> 5;
    const u32 smb = smem_u32(sm);

    // ---- stage Q (scaled, bf16 split) into smem ----
    {
        const float* qbase = g_qT + (size_t)i0 * DIMC + h * 64;
        for (int idx = tid; idx < 2048; idx += 128) {
            int r = idx >> 5, c2 = idx & 31;
            const float* qp = qbase + (size_t)r * DIMC + 2 * c2;
            float a = qp[0] * QSCL, b = qp[1] * QSCL;
            float ah = bfhi(a), bh = bfhi(b);
            *(u32*)(sm + O_QHI + r * SMSTRIDE + c2 * 4) = pack_bf16(ah, bh);
            *(u32*)(sm + O_QLO + r * SMSTRIDE + c2 * 4) = pack_bf16(a - ah, b - bh);
        }
    }
    __syncthreads();

    // ---- Q fragments (4 k-blocks of 16) ----
    u32 qh[4][4], ql[4][4];
    {
        int qrow = wid * 16 + (lane & 7) + ((lane >> 3) & 1) * 8;
        u32 qoff = smb + qrow * SMSTRIDE + ((lane >> 4) & 1) * 16;
        #pragma unroll
        for (int kb = 0; kb < 4; kb++) {
            ldsm_x4(qoff + O_QHI + kb * 32, qh[kb][0], qh[kb][1], qh[kb][2], qh[kb][3]);
            ldsm_x4(qoff + O_QLO + kb * 32, ql[kb][0], ql[kb][1], ql[kb][2], ql[kb][3]);
        }
    }

    const __nv_bfloat16* khb = g_khi + (size_t)s * M_SEQ * INNER + h * 64;
    const __nv_bfloat16* klb = g_klo + (size_t)s * M_SEQ * INNER + h * 64;
    const __nv_bfloat16* vhb = g_vhi + (size_t)s * M_SEQ * INNER + h * 64;
    const __nv_bfloat16* vlb = g_vlo + (size_t)s * M_SEQ * INNER + h * 64;

    const u32 lpK = (lane & 7) * SMSTRIDE + ((lane >> 3) & 1) * 16;
    const u32 lpV = (lane & 7) * SMSTRIDE + ((lane >> 3) & 1) * (8 * SMSTRIDE);

    float oacc[8][4];
    #pragma unroll
    for (int nd = 0; nd < 8; nd++)
        #pragma unroll
        for (int u = 0; u < 4; u++) oacc[nd][u] = 0.f;
    float mA = -1e30f, mB = -1e30f, lA = 0.f, lB = 0.f;

    for (int j0 = 0; j0 < M_SEQ; j0 += 64) {
        __syncthreads();   // prior tile's ldmatrix reads done (also orders Q-frag reads)
        for (int idx = tid; idx < 2048; idx += 128) {
            int r = idx >> 5, c2 = idx & 31;
            size_t go = (size_t)(j0 + r) * INNER + 2 * c2;
            u32 so = r * SMSTRIDE + c2 * 4;
            *(u32*)(sm + O_KHI + so) = *(const u32*)&khb[go];
            *(u32*)(sm + O_KLO + so) = *(const u32*)&klb[go];
            *(u32*)(sm + O_VHI + so) = *(const u32*)&vhb[go];
            *(u32*)(sm + O_VLO + so) = *(const u32*)&vlb[go];
        }
        __syncthreads();

        // ---- S = Q K^T (hh + lh + hl) ----
        float sacc[8][4];
        #pragma unroll
        for (int nb = 0; nb < 8; nb++)
            #pragma unroll
            for (int u = 0; u < 4; u++) sacc[nb][u] = 0.f;
        #pragma unroll
        for (int kb = 0; kb < 4; kb++) {
            #pragma unroll
            for (int nb = 0; nb < 8; nb++) {
                u32 b0, b1, c0, c1;
                ldsm_x2(smb + O_KHI + lpK + nb * (8 * SMSTRIDE) + kb * 32, b0, b1);
                mma16816(sacc[nb], qh[kb][0], qh[kb][1], qh[kb][2], qh[kb][3], b0, b1);
                mma16816(sacc[nb], ql[kb][0], ql[kb][1], ql[kb][2], ql[kb][3], b0, b1);
                ldsm_x2(smb + O_KLO + lpK + nb * (8 * SMSTRIDE) + kb * 32, c0, c1);
                mma16816(sacc[nb], qh[kb][0], qh[kb][1], qh[kb][2], qh[kb][3], c0, c1);
            }
        }

        // ---- online softmax (base-2). Rows: A = lane/4, B = lane/4+8 ----
        float tA = -1e30f, tB = -1e30f;
        #pragma unroll
        for (int nb = 0; nb < 8; nb++) {
            tA = fmaxf(tA, fmaxf(sacc[nb][0], sacc[nb][1]));
            tB = fmaxf(tB, fmaxf(sacc[nb][2], sacc[nb][3]));
        }
        tA = fmaxf(tA, __shfl_xor_sync(0xffffffffu, tA, 1));
        tA = fmaxf(tA, __shfl_xor_sync(0xffffffffu, tA, 2));
        tB = fmaxf(tB, __shfl_xor_sync(0xffffffffu, tB, 1));
        tB = fmaxf(tB, __shfl_xor_sync(0xffffffffu, tB, 2));
        float mAn = fmaxf(mA, tA), mBn = fmaxf(mB, tB);
        float cA = ex2f(mA - mAn), cB = ex2f(mB - mBn);
        mA = mAn; mB = mBn;
        float sA = 0.f, sB = 0.f;
        #pragma unroll
        for (int nb = 0; nb < 8; nb++) {
            sacc[nb][0] = ex2f(sacc[nb][0] - mAn);
            sacc[nb][1] = ex2f(sacc[nb][1] - mAn);
            sacc[nb][2] = ex2f(sacc[nb][2] - mBn);
            sacc[nb][3] = ex2f(sacc[nb][3] - mBn);
            sA += sacc[nb][0] + sacc[nb][1];
            sB += sacc[nb][2] + sacc[nb][3];
        }
        sA += __shfl_xor_sync(0xffffffffu, sA, 1);
        sA += __shfl_xor_sync(0xffffffffu, sA, 2);
        sB += __shfl_xor_sync(0xffffffffu, sB, 1);
        sB += __shfl_xor_sync(0xffffffffu, sB, 2);
        lA = lA * cA + sA;
        lB = lB * cB + sB;
        #pragma unroll
        for (int nd = 0; nd < 8; nd++) {
            oacc[nd][0] *= cA; oacc[nd][1] *= cA;
            oacc[nd][2] *= cB; oacc[nd][3] *= cB;
        }

        // ---- O += P V (ph*vh + pl*vh + ph*vl) ----
        #pragma unroll
        for (int kb = 0; kb < 4; kb++) {
            const float* pL = sacc[2 * kb];
            const float* pH = sacc[2 * kb + 1];
            float h00 = bfhi(pL[0]), h01 = bfhi(pL[1]), h02 = bfhi(pL[2]), h03 = bfhi(pL[3]);
            float h10 = bfhi(pH[0]), h11 = bfhi(pH[1]), h12 = bfhi(pH[2]), h13 = bfhi(pH[3]);
            u32 a0 = pack_bf16(h00, h01), a1 = pack_bf16(h02, h03);
            u32 a2 = pack_bf16(h10, h11), a3 = pack_bf16(h12, h13);
            u32 e0 = pack_bf16(pL[0] - h00, pL[1] - h01);
            u32 e1 = pack_bf16(pL[2] - h02, pL[3] - h03);
            u32 e2 = pack_bf16(pH[0] - h10, pH[1] - h11);
            u32 e3 = pack_bf16(pH[2] - h12, pH[3] - h13);
            #pragma unroll
            for (int nd = 0; nd < 8; nd++) {
                u32 b0, b1, c0, c1;
                ldsm_x2_t(smb + O_VHI + lpV + kb * (16 * SMSTRIDE) + nd * 16, b0, b1);
                mma16816(oacc[nd], a0, a1, a2, a3, b0, b1);
                mma16816(oacc[nd], e0, e1, e2, e3, b0, b1);
                ldsm_x2_t(smb + O_VLO + lpV + kb * (16 * SMSTRIDE) + nd * 16, c0, c1);
                mma16816(oacc[nd], a0, a1, a2, a3, c0, c1);
            }
        }
    }

    // ---- epilogue: normalize, stage [i][d] in smem, coalesced store ----
    __syncthreads();
    float invA = 1.f / lA, invB = 1.f / lB;
    float* Os = (float*)sm;          // 64 x 72 floats (aliases K region)
    const int rA = wid * 16 + (lane >> 2), rB = rA + 8;
    #pragma unroll
    for (int nd = 0; nd < 8; nd++) {
        int col = nd * 8 + (lane & 3) * 2;
        Os[rA * 72 + col]     = oacc[nd][0] * invA;
        Os[rA * 72 + col + 1] = oacc[nd][1] * invA;
        Os[rB * 72 + col]     = oacc[nd][2] * invB;
        Os[rB * 72 + col + 1] = oacc[nd][3] * invB;
    }
    __syncthreads();
    float* ob = g_att + ((size_t)s * INNER + h * 64) * N_SEQ + i0;
    #pragma unroll 4
    for (int it = 0; it < 32; it++) {
        int d = it * 2 + (tid >> 6);
        int i = tid & 63;
        ob[(size_t)d * N_SEQ + i] = Os[i * 72 + d];
    }
}

// ================= Kernel 6: stream-mean + Wo GEMM + bias ======================
__global__ __launch_bounds__(256) void outproj_kernel(
    const float* __restrict__ Wo, const float* __restrict__ bo,
    float* __restrict__ out)
{
    __shared__ float As[16][68];
    __shared__ float Bs[16][68];
    const int d0 = blockIdx.y * 64;
    const int i0 = blockIdx.x * 64;
    const int tid = threadIdx.x;
    const int tx = tid & 15, ty = tid >> 4;

    ull acc2[4][2];
    #pragma unroll
    for (int a = 0; a < 4; a++) { acc2[a][0] = 0ULL; acc2[a][1] = 0ULL; }

    for (int k0 = 0; k0 < 512; k0 += 16) {
        {
            int d = tid >> 2, k = (tid & 3) * 4;
            float4 w = *(const float4*)&Wo[(d0 + d) * INNER + k0 + k];
            As[k+0][d] = w.x; As[k+1][d] = w.y; As[k+2][d] = w.z; As[k+3][d] = w.w;
        }
        {
            int k = tid >> 4, i4 = (tid & 15) * 4;
            const float* a0 = &g_att[(size_t)(k0 + k) * N_SEQ + i0 + i4];
            const float* a1 = a0 + (size_t)INNER * N_SEQ;
            float4 v0 = *(const float4*)a0;
            float4 v1 = *(const float4*)a1;
            Bs[k][i4+0] = 0.5f * (v0.x + v1.x);
            Bs[k][i4+1] = 0.5f * (v0.y + v1.y);
            Bs[k][i4+2] = 0.5f * (v0.z + v1.z);
            Bs[k][i4+3] = 0.5f * (v0.w + v1.w);
        }
        __syncthreads();
        #pragma unroll
        for (int kk = 0; kk < 16; kk++) {
            ull b0 = *(const ull*)&Bs[kk][tx*4];
            ull b1 = *(const ull*)&Bs[kk][tx*4+2];
            #pragma unroll
            for (int u = 0; u < 4; u++) {
                ull av = splat2(As[kk][ty*4 + u]);
                acc2[u][0] = fma2(av, b0, acc2[u][0]);
                acc2[u][1] = fma2(av, b1, acc2[u][1]);
            }
        }
        __syncthreads();
    }
    #pragma unroll
    for (int ai = 0; ai < 4; ai++) {
        float bias = bo[d0 + ty*4 + ai];
        float lo, hi;
        unpack2(acc2[ai][0], lo, hi);
        out[(size_t)(i0 + tx*4 + 0) * DIMC + d0 + ty*4 + ai] = lo + bias;
        out[(size_t)(i0 + tx*4 + 1) * DIMC + d0 + ty*4 + ai] = hi + bias;
        unpack2(acc2[ai][1], lo, hi);
        out[(size_t)(i0 + tx*4 + 2) * DIMC + d0 + ty*4 + ai] = lo + bias;
        out[(size_t)(i0 + tx*4 + 3) * DIMC + d0 + ty*4 + ai] = hi + bias;
    }
}

// ================= launch ======================================================
extern "C" void kernel_launch(void* const* d_in, const int* in_sizes, int n_in,
                              void* d_out, int out_size)
{
    const float* x   = (const float*)d_in[0];
    const float* px  = (const float*)d_in[1];
    const float* Wq  = (const float*)d_in[2];
    const float* Wk  = (const float*)d_in[3];
    const float* Wv  = (const float*)d_in[4];
    const float* Wo  = (const float*)d_in[5];
    const float* bo  = (const float*)d_in[6];
    const float* Wdw = (const float*)d_in[7];
    const float* bdw = (const float*)d_in[8];
    const float* Wp  = (const float*)d_in[9];
    float* out = (float*)d_out;

    qproj_kernel<<<dim3(64, 8), 256>>>(x, px, Wq);
    offset_kernel<<<dim3(8, 8), 128>>>(Wdw, bdw, Wp);
    gridsample_kernel<<<4096, 256>>>(x, px);
    kvproj_kernel<<<dim3(16, 8, 2), 256>>>(Wk, 0);
    kvproj_kernel<<<dim3(16, 8, 2), 256>>>(Wv, 1);
    attn_kernel<<<dim3(64, HEADS, 2), 128>>>();
    outproj_kernel<<<dim3(64, 8), 256>>>(Wo, bo, out);
}

// round 6
// speedup vs baseline: 2.0995x; 1.1524x over previous
#include <cuda_runtime.h>
#include <cuda_bf16.h>
#include <math.h>

typedef unsigned int u32;
typedef unsigned long long u64;
typedef unsigned long long ull;

#define N_SEQ 4096
#define M_SEQ 1024
#define DIMC  512
#define INNER 512
#define HEADS 8
#define GROUPS 8

// ---------------- warp-MMA helpers (sm_80-class, no arch-suffix gating) --------
__device__ __forceinline__ u32 smem_u32(const void* p) {
    u32 a;
    asm("{ .reg .u64 t; cvta.to.shared.u64 t, %1; cvt.u32.u64 %0, t; }" : "=r"(a) : "l"(p));
    return a;
}
__device__ __forceinline__ float ex2f(float x) {
    float r; asm("ex2.approx.ftz.f32 %0, %1;" : "=f"(r) : "f"(x)); return r;
}
__device__ __forceinline__ void ldsm_x4(u32 addr, u32& r0, u32& r1, u32& r2, u32& r3) {
    asm volatile("ldmatrix.sync.aligned.m8n8.x4.shared.b16 {%0,%1,%2,%3}, [%4];"
        : "=r"(r0), "=r"(r1), "=r"(r2), "=r"(r3) : "r"(addr));
}
__device__ __forceinline__ void ldsm_x2(u32 addr, u32& r0, u32& r1) {
    asm volatile("ldmatrix.sync.aligned.m8n8.x2.shared.b16 {%0,%1}, [%2];"
        : "=r"(r0), "=r"(r1) : "r"(addr));
}
__device__ __forceinline__ void ldsm_x2_t(u32 addr, u32& r0, u32& r1) {
    asm volatile("ldmatrix.sync.aligned.m8n8.x2.trans.shared.b16 {%0,%1}, [%2];"
        : "=r"(r0), "=r"(r1) : "r"(addr));
}
__device__ __forceinline__ void mma16816(float* c, u32 a0, u32 a1, u32 a2, u32 a3,
                                         u32 b0, u32 b1) {
    asm volatile(
        "mma.sync.aligned.m16n8k16.row.col.f32.bf16.bf16.f32 "
        "{%0,%1,%2,%3}, {%4,%5,%6,%7}, {%8,%9}, {%0,%1,%2,%3};"
        : "+f"(c[0]), "+f"(c[1]), "+f"(c[2]), "+f"(c[3])
        : "r"(a0), "r"(a1), "r"(a2), "r"(a3), "r"(b0), "r"(b1));
}
__device__ __forceinline__ u32 pack_bf16(float a, float b) {
    return ((u32)__bfloat16_as_ushort(__float2bfloat16(b)) << 16) |
           (u32)__bfloat16_as_ushort(__float2bfloat16(a));
}
__device__ __forceinline__ float bfhi(float x) {
    return __bfloat162float(__float2bfloat16(x));
}

// ---------------- f32x2 helpers for scalar GEMMs -------------------------------
__device__ __forceinline__ ull splat2(float x) {
    ull r; asm("mov.b64 %0, {%1, %1};" : "=l"(r) : "r"(__float_as_uint(x))); return r;
}
__device__ __forceinline__ ull fma2(ull a, ull b, ull c) {
    ull d; asm("fma.rn.f32x2 %0, %1, %2, %3;" : "=l"(d) : "l"(a), "l"(b), "l"(c)); return d;
}
__device__ __forceinline__ void unpack2(ull v, float& lo, float& hi) {
    u32 l, h; asm("mov.b64 {%0, %1}, %2;" : "=r"(l), "=r"(h) : "l"(v));
    lo = __uint_as_float(l); hi = __uint_as_float(h);
}

// ---------------- scratch (static device globals) ------------------------------
__device__ float g_qT[N_SEQ * DIMC];                 // q[i][c]
__device__ float g_pos[GROUPS * M_SEQ];
__device__ float g_kvT[2 * M_SEQ * INNER];           // kv[s][t][ch]
__device__ __nv_bfloat16 g_khi[2 * M_SEQ * INNER];   // k hi  [s][t][c]
__device__ __nv_bfloat16 g_klo[2 * M_SEQ * INNER];   // k lo
__device__ __nv_bfloat16 g_vhi[2 * M_SEQ * INNER];   // v hi  [s][t][c]
__device__ __nv_bfloat16 g_vlo[2 * M_SEQ * INNER];   // v lo
__device__ float g_att[2 * N_SEQ * INNER];           // attn out [s][i][c]

#define SMSTRIDE 144          // 72 bf16 per row (pad 8 -> conflict-free ldmatrix)

// ================= Kernel 1: grouped 1x1 q projection (scalar FFMA2) ===========
__global__ __launch_bounds__(256) void qproj_kernel(
    const float* __restrict__ x, const float* __restrict__ px,
    const float* __restrict__ Wq)
{
    __shared__ float As[16][68];
    __shared__ float Bs[16][68];
    const int g  = blockIdx.y;
    const int i0 = blockIdx.x * 64;
    const int c0 = g * 64;
    const float* src  = (g < 4) ? px : x;
    const int   base  = (g & 3) * 128;
    const int tid = threadIdx.x;
    const int tx = tid & 15, ty = tid >> 4;

    ull acc2[4][2];
    #pragma unroll
    for (int a = 0; a < 4; a++) { acc2[a][0] = 0ULL; acc2[a][1] = 0ULL; }

    for (int k0 = 0; k0 < 128; k0 += 16) {
        {
            int c = tid >> 2, k = (tid & 3) * 4;
            float4 w = *(const float4*)&Wq[(c0 + c) * 128 + k0 + k];
            As[k+0][c] = w.x; As[k+1][c] = w.y; As[k+2][c] = w.z; As[k+3][c] = w.w;
        }
        {
            int i = tid >> 2, k = (tid & 3) * 4;
            float4 b4 = *(const float4*)&src[(i0 + i) * DIMC + base + k0 + k];
            Bs[k+0][i] = b4.x; Bs[k+1][i] = b4.y; Bs[k+2][i] = b4.z; Bs[k+3][i] = b4.w;
        }
        __syncthreads();
        #pragma unroll
        for (int kk = 0; kk < 16; kk++) {
            ull b0 = *(const ull*)&Bs[kk][tx*4];
            ull b1 = *(const ull*)&Bs[kk][tx*4+2];
            #pragma unroll
            for (int u = 0; u < 4; u++) {
                ull av = splat2(As[kk][ty*4 + u]);
                acc2[u][0] = fma2(av, b0, acc2[u][0]);
                acc2[u][1] = fma2(av, b1, acc2[u][1]);
            }
        }
        __syncthreads();
    }
    #pragma unroll
    for (int ai = 0; ai < 4; ai++) {
        float v0, v1, v2, v3;
        unpack2(acc2[ai][0], v0, v1);
        unpack2(acc2[ai][1], v2, v3);
        const int c = c0 + ty*4 + ai;
        g_qT[(size_t)(i0 + tx*4 + 0) * DIMC + c] = v0;
        g_qT[(size_t)(i0 + tx*4 + 1) * DIMC + c] = v1;
        g_qT[(size_t)(i0 + tx*4 + 2) * DIMC + c] = v2;
        g_qT[(size_t)(i0 + tx*4 + 3) * DIMC + c] = v3;
    }
}

// ================= Kernel 2: offset network ====================================
__global__ __launch_bounds__(128) void offset_kernel(
    const float* __restrict__ Wdw, const float* __restrict__ bdw,
    const float* __restrict__ Wp)
{
    const int g = blockIdx.y;
    const int t = blockIdx.x * 128 + threadIdx.x;
    const int pbase = 4 * t - 1;
    float s = 0.f;
    for (int c = 0; c < 64; c++) {
        float hv = bdw[c];
        #pragma unroll
        for (int k = 0; k < 6; k++) {
            int p = pbase + k;
            if (p >= 0 && p < N_SEQ) hv += Wdw[c * 6 + k] * g_qT[(size_t)p * DIMC + g * 64 + c];
        }
        hv = 0.5f * hv * (1.f + erff(hv * 0.7071067811865476f));
        s += Wp[c] * hv;
    }
    float off = tanhf(s) * 4.0f;
    float vg  = 2.0f * ((float)t + off) / 1023.0f - 1.0f;
    float pos = ((vg + 1.0f) * (float)N_SEQ - 1.0f) * 0.5f;
    g_pos[g * M_SEQ + t] = pos;
}

// ================= Kernel 3: 1-D bilinear grid sample ==========================
__global__ __launch_bounds__(256) void gridsample_kernel(
    const float* __restrict__ x, const float* __restrict__ px)
{
    const int tid = blockIdx.x * 256 + threadIdx.x;
    const int c    = tid & 63;
    const int unit = tid >> 6;
    const int t  = unit & (M_SEQ - 1);
    const int sg = unit >> 10;
    const int g  = sg & 7;
    const int s  = sg >> 3;
    const float* src = (s == 0) ? px : x;
    const float pos = g_pos[g * M_SEQ + t];
    const float x0 = floorf(pos);
    const float w1 = pos - x0;
    const int p0 = (int)x0;
    const int ch = g * 64 + c;
    float v = 0.f;
    if (p0 >= 0 && p0 < N_SEQ)           v += (1.f - w1) * src[p0 * DIMC + ch];
    if (p0 + 1 >= 0 && p0 + 1 < N_SEQ)   v += w1 * src[(p0 + 1) * DIMC + ch];
    g_kvT[(size_t)(s * M_SEQ + t) * INNER + ch] = v;
}

// ================= Kernel 4: k/v projection via warp-MMA =======================
// out[t][c] = sum_j W[c][j] * kv[t][c0+j]   (K=64, one chunk)
// A = kv[t][j] row-major, B = W[c][j] [n][k]. Emits bf16 hi/lo directly.
#define KV_AHI 0
#define KV_ALO 9216
#define KV_BHI 18432
#define KV_BLO 27648

__global__ __launch_bounds__(128) void kvproj_mma_kernel(
    const float* __restrict__ Wk, const float* __restrict__ Wv)
{
    __shared__ __align__(16) char sm[36864];
    const int t0 = blockIdx.x * 64;
    const int g  = blockIdx.y;
    const int s  = blockIdx.z & 1;
    const int which = blockIdx.z >> 1;
    const int c0 = g * 64;
    const float* W = which ? Wv : Wk;
    __nv_bfloat16* ohi = which ? g_vhi : g_khi;
    __nv_bfloat16* olo = which ? g_vlo : g_klo;
    const int tid = threadIdx.x;
    const int lane = tid & 31, wid = tid >> 5;
    const u32 smb = smem_u32(sm);

    // stage A (kv) and B (W), bf16 split
    for (int idx = tid; idx < 2048; idx += 128) {
        int r = idx >> 5, c2 = idx & 31;
        float2 a = *(const float2*)&g_kvT[(size_t)(s * M_SEQ + t0 + r) * INNER + c0 + 2 * c2];
        float ah = bfhi(a.x), bh = bfhi(a.y);
        u32 so = r * SMSTRIDE + c2 * 4;
        *(u32*)(sm + KV_AHI + so) = pack_bf16(ah, bh);
        *(u32*)(sm + KV_ALO + so) = pack_bf16(a.x - ah, a.y - bh);
        float2 w = *(const float2*)&W[(c0 + r) * 64 + 2 * c2];
        float wh = bfhi(w.x), xh = bfhi(w.y);
        *(u32*)(sm + KV_BHI + so) = pack_bf16(wh, xh);
        *(u32*)(sm + KV_BLO + so) = pack_bf16(w.x - wh, w.y - xh);
    }
    __syncthreads();

    float acc[8][4];
    #pragma unroll
    for (int nb = 0; nb < 8; nb++)
        #pragma unroll
        for (int u = 0; u < 4; u++) acc[nb][u] = 0.f;

    const u32 apos = (wid * 16 + (lane & 7) + ((lane >> 3) & 1) * 8) * SMSTRIDE
                   + ((lane >> 4) & 1) * 16;
    const u32 bpos = (lane & 7) * SMSTRIDE + ((lane >> 3) & 1) * 16;

    #pragma unroll
    for (int kb = 0; kb < 4; kb++) {
        u32 ah0, ah1, ah2, ah3, al0, al1, al2, al3;
        ldsm_x4(smb + KV_AHI + apos + kb * 32, ah0, ah1, ah2, ah3);
        ldsm_x4(smb + KV_ALO + apos + kb * 32, al0, al1, al2, al3);
        #pragma unroll
        for (int nb = 0; nb < 8; nb++) {
            u32 b0, b1, c0r, c1r;
            ldsm_x2(smb + KV_BHI + bpos + nb * (8 * SMSTRIDE) + kb * 32, b0, b1);
            mma16816(acc[nb], ah0, ah1, ah2, ah3, b0, b1);
            mma16816(acc[nb], al0, al1, al2, al3, b0, b1);
            ldsm_x2(smb + KV_BLO + bpos + nb * (8 * SMSTRIDE) + kb * 32, c0r, c1r);
            mma16816(acc[nb], ah0, ah1, ah2, ah3, c0r, c1r);
        }
    }

    // epilogue: split fp32 -> bf16 hi/lo packed stores
    const int rA = wid * 16 + (lane >> 2), rB = rA + 8;
    #pragma unroll
    for (int nb = 0; nb < 8; nb++) {
        int col = nb * 8 + (lane & 3) * 2;
        float v0 = acc[nb][0], v1 = acc[nb][1];
        float h0 = bfhi(v0), h1 = bfhi(v1);
        size_t iA = (size_t)(s * M_SEQ + t0 + rA) * INNER + c0 + col;
        *(u32*)&ohi[iA] = pack_bf16(h0, h1);
        *(u32*)&olo[iA] = pack_bf16(v0 - h0, v1 - h1);
        float v2 = acc[nb][2], v3 = acc[nb][3];
        float h2 = bfhi(v2), h3 = bfhi(v3);
        size_t iB = (size_t)(s * M_SEQ + t0 + rB) * INNER + c0 + col;
        *(u32*)&ohi[iB] = pack_bf16(h2, h3);
        *(u32*)&olo[iB] = pack_bf16(v2 - h2, v3 - h3);
    }
}

// ================= Kernel 5: warp-MMA flash attention ==========================
// CTA: 64 q-rows, 4 warps x 16 rows. Bc=64. bf16 3-term split both GEMMs.
#define O_KHI 0
#define O_KLO 9216
#define O_VHI 18432
#define O_VLO 27648
#define O_QHI 0               // Q staging aliases K region (used before loop only)
#define O_QLO 9216
#define SM_TOTAL 36864
#define QSCL 0.1803368801111204f   // 0.125 * log2(e)

__global__ __launch_bounds__(128) void attn_kernel()
{
    __shared__ __align__(16) char sm[SM_TOTAL];
    const int i0 = blockIdx.x * 64;
    const int h  = blockIdx.y;
    const int s  = blockIdx.z;
    const int tid = threadIdx.x;
    const int lane = tid & 31;
    const int wid = tid >> 5;
    const u32 smb = smem_u32(sm);

    // ---- stage Q (scaled, bf16 split) into smem ----
    {
        const float* qbase = g_qT + (size_t)i0 * DIMC + h * 64;
        for (int idx = tid; idx < 2048; idx += 128) {
            int r = idx >> 5, c2 = idx & 31;
            const float* qp = qbase + (size_t)r * DIMC + 2 * c2;
            float a = qp[0] * QSCL, b = qp[1] * QSCL;
            float ah = bfhi(a), bh = bfhi(b);
            *(u32*)(sm + O_QHI + r * SMSTRIDE + c2 * 4) = pack_bf16(ah, bh);
            *(u32*)(sm + O_QLO + r * SMSTRIDE + c2 * 4) = pack_bf16(a - ah, b - bh);
        }
    }
    __syncthreads();

    // ---- Q fragments (4 k-blocks of 16) ----
    u32 qh[4][4], ql[4][4];
    {
        int qrow = wid * 16 + (lane & 7) + ((lane >> 3) & 1) * 8;
        u32 qoff = smb + qrow * SMSTRIDE + ((lane >> 4) & 1) * 16;
        #pragma unroll
        for (int kb = 0; kb < 4; kb++) {
            ldsm_x4(qoff + O_QHI + kb * 32, qh[kb][0], qh[kb][1], qh[kb][2], qh[kb][3]);
            ldsm_x4(qoff + O_QLO + kb * 32, ql[kb][0], ql[kb][1], ql[kb][2], ql[kb][3]);
        }
    }

    const __nv_bfloat16* khb = g_khi + (size_t)s * M_SEQ * INNER + h * 64;
    const __nv_bfloat16* klb = g_klo + (size_t)s * M_SEQ * INNER + h * 64;
    const __nv_bfloat16* vhb = g_vhi + (size_t)s * M_SEQ * INNER + h * 64;
    const __nv_bfloat16* vlb = g_vlo + (size_t)s * M_SEQ * INNER + h * 64;

    const u32 lpK = (lane & 7) * SMSTRIDE + ((lane >> 3) & 1) * 16;
    const u32 lpV = (lane & 7) * SMSTRIDE + ((lane >> 3) & 1) * (8 * SMSTRIDE);

    float oacc[8][4];
    #pragma unroll
    for (int nd = 0; nd < 8; nd++)
        #pragma unroll
        for (int u = 0; u < 4; u++) oacc[nd][u] = 0.f;
    float mA = -1e30f, mB = -1e30f, lA = 0.f, lB = 0.f;

    for (int j0 = 0; j0 < M_SEQ; j0 += 64) {
        __syncthreads();   // prior tile's ldmatrix reads done (also orders Q-frag reads)
        for (int idx = tid; idx < 2048; idx += 128) {
            int r = idx >> 5, c2 = idx & 31;
            size_t go = (size_t)(j0 + r) * INNER + 2 * c2;
            u32 so = r * SMSTRIDE + c2 * 4;
            *(u32*)(sm + O_KHI + so) = *(const u32*)&khb[go];
            *(u32*)(sm + O_KLO + so) = *(const u32*)&klb[go];
            *(u32*)(sm + O_VHI + so) = *(const u32*)&vhb[go];
            *(u32*)(sm + O_VLO + so) = *(const u32*)&vlb[go];
        }
        __syncthreads();

        // ---- S = Q K^T (hh + lh + hl) ----
        float sacc[8][4];
        #pragma unroll
        for (int nb = 0; nb < 8; nb++)
            #pragma unroll
            for (int u = 0; u < 4; u++) sacc[nb][u] = 0.f;
        #pragma unroll
        for (int kb = 0; kb < 4; kb++) {
            #pragma unroll
            for (int nb = 0; nb < 8; nb++) {
                u32 b0, b1, c0, c1;
                ldsm_x2(smb + O_KHI + lpK + nb * (8 * SMSTRIDE) + kb * 32, b0, b1);
                mma16816(sacc[nb], qh[kb][0], qh[kb][1], qh[kb][2], qh[kb][3], b0, b1);
                mma16816(sacc[nb], ql[kb][0], ql[kb][1], ql[kb][2], ql[kb][3], b0, b1);
                ldsm_x2(smb + O_KLO + lpK + nb * (8 * SMSTRIDE) + kb * 32, c0, c1);
                mma16816(sacc[nb], qh[kb][0], qh[kb][1], qh[kb][2], qh[kb][3], c0, c1);
            }
        }

        // ---- online softmax (base-2). Rows: A = lane/4, B = lane/4+8 ----
        float tA = -1e30f, tB = -1e30f;
        #pragma unroll
        for (int nb = 0; nb < 8; nb++) {
            tA = fmaxf(tA, fmaxf(sacc[nb][0], sacc[nb][1]));
            tB = fmaxf(tB, fmaxf(sacc[nb][2], sacc[nb][3]));
        }
        tA = fmaxf(tA, __shfl_xor_sync(0xffffffffu, tA, 1));
        tA = fmaxf(tA, __shfl_xor_sync(0xffffffffu, tA, 2));
        tB = fmaxf(tB, __shfl_xor_sync(0xffffffffu, tB, 1));
        tB = fmaxf(tB, __shfl_xor_sync(0xffffffffu, tB, 2));
        float mAn = fmaxf(mA, tA), mBn = fmaxf(mB, tB);
        float cA = ex2f(mA - mAn), cB = ex2f(mB - mBn);
        mA = mAn; mB = mBn;
        float sA = 0.f, sB = 0.f;
        #pragma unroll
        for (int nb = 0; nb < 8; nb++) {
            sacc[nb][0] = ex2f(sacc[nb][0] - mAn);
            sacc[nb][1] = ex2f(sacc[nb][1] - mAn);
            sacc[nb][2] = ex2f(sacc[nb][2] - mBn);
            sacc[nb][3] = ex2f(sacc[nb][3] - mBn);
            sA += sacc[nb][0] + sacc[nb][1];
            sB += sacc[nb][2] + sacc[nb][3];
        }
        sA += __shfl_xor_sync(0xffffffffu, sA, 1);
        sA += __shfl_xor_sync(0xffffffffu, sA, 2);
        sB += __shfl_xor_sync(0xffffffffu, sB, 1);
        sB += __shfl_xor_sync(0xffffffffu, sB, 2);
        lA = lA * cA + sA;
        lB = lB * cB + sB;
        #pragma unroll
        for (int nd = 0; nd < 8; nd++) {
            oacc[nd][0] *= cA; oacc[nd][1] *= cA;
            oacc[nd][2] *= cB; oacc[nd][3] *= cB;
        }

        // ---- O += P V (ph*vh + pl*vh + ph*vl) ----
        #pragma unroll
        for (int kb = 0; kb < 4; kb++) {
            const float* pL = sacc[2 * kb];
            const float* pH = sacc[2 * kb + 1];
            float h00 = bfhi(pL[0]), h01 = bfhi(pL[1]), h02 = bfhi(pL[2]), h03 = bfhi(pL[3]);
            float h10 = bfhi(pH[0]), h11 = bfhi(pH[1]), h12 = bfhi(pH[2]), h13 = bfhi(pH[3]);
            u32 a0 = pack_bf16(h00, h01), a1 = pack_bf16(h02, h03);
            u32 a2 = pack_bf16(h10, h11), a3 = pack_bf16(h12, h13);
            u32 e0 = pack_bf16(pL[0] - h00, pL[1] - h01);
            u32 e1 = pack_bf16(pL[2] - h02, pL[3] - h03);
            u32 e2 = pack_bf16(pH[0] - h10, pH[1] - h11);
            u32 e3 = pack_bf16(pH[2] - h12, pH[3] - h13);
            #pragma unroll
            for (int nd = 0; nd < 8; nd++) {
                u32 b0, b1, c0, c1;
                ldsm_x2_t(smb + O_VHI + lpV + kb * (16 * SMSTRIDE) + nd * 16, b0, b1);
                mma16816(oacc[nd], a0, a1, a2, a3, b0, b1);
                mma16816(oacc[nd], e0, e1, e2, e3, b0, b1);
                ldsm_x2_t(smb + O_VLO + lpV + kb * (16 * SMSTRIDE) + nd * 16, c0, c1);
                mma16816(oacc[nd], a0, a1, a2, a3, c0, c1);
            }
        }
    }

    // ---- epilogue: normalize and store directly to g_att[s][i][c] ----
    float invA = 1.f / lA, invB = 1.f / lB;
    const int rA = wid * 16 + (lane >> 2), rB = rA + 8;
    float* oA = g_att + (size_t)s * N_SEQ * INNER + (size_t)(i0 + rA) * INNER + h * 64;
    float* oB = g_att + (size_t)s * N_SEQ * INNER + (size_t)(i0 + rB) * INNER + h * 64;
    #pragma unroll
    for (int nd = 0; nd < 8; nd++) {
        int col = nd * 8 + (lane & 3) * 2;
        *(float2*)&oA[col] = make_float2(oacc[nd][0] * invA, oacc[nd][1] * invA);
        *(float2*)&oB[col] = make_float2(oacc[nd][2] * invB, oacc[nd][3] * invB);
    }
}

// ================= Kernel 6: stream-mean + Wo GEMM (warp-MMA) ==================
// out[i][d] = bo[d] + sum_c Wo[d][c] * 0.5*(att0[i][c]+att1[i][c])
#define OP_AHI 0
#define OP_ALO 9216
#define OP_BHI 18432
#define OP_BLO 27648

__global__ __launch_bounds__(128) void outproj_mma_kernel(
    const float* __restrict__ Wo, const float* __restrict__ bo,
    float* __restrict__ out)
{
    __shared__ __align__(16) char sm[36864];
    const int i0 = blockIdx.x * 64;
    const int d0 = blockIdx.y * 64;
    const int tid = threadIdx.x;
    const int lane = tid & 31, wid = tid >> 5;
    const u32 smb = smem_u32(sm);

    float acc[8][4];
    #pragma unroll
    for (int nb = 0; nb < 8; nb++)
        #pragma unroll
        for (int u = 0; u < 4; u++) acc[nb][u] = 0.f;

    const u32 apos = (wid * 16 + (lane & 7) + ((lane >> 3) & 1) * 8) * SMSTRIDE
                   + ((lane >> 4) & 1) * 16;
    const u32 bpos = (lane & 7) * SMSTRIDE + ((lane >> 3) & 1) * 16;

    for (int k0 = 0; k0 < 512; k0 += 64) {
        __syncthreads();   // previous chunk's frag reads done
        for (int idx = tid; idx < 2048; idx += 128) {
            int r = idx >> 5, c2 = idx & 31;
            const float* a0p = &g_att[(size_t)(i0 + r) * INNER + k0 + 2 * c2];
            float2 u0 = *(const float2*)a0p;
            float2 u1 = *(const float2*)(a0p + (size_t)N_SEQ * INNER);
            float ax = 0.5f * (u0.x + u1.x), ay = 0.5f * (u0.y + u1.y);
            float ah = bfhi(ax), bh = bfhi(ay);
            u32 so = r * SMSTRIDE + c2 * 4;
            *(u32*)(sm + OP_AHI + so) = pack_bf16(ah, bh);
            *(u32*)(sm + OP_ALO + so) = pack_bf16(ax - ah, ay - bh);
            float2 w = *(const float2*)&Wo[(d0 + r) * INNER + k0 + 2 * c2];
            float wh = bfhi(w.x), xh = bfhi(w.y);
            *(u32*)(sm + OP_BHI + so) = pack_bf16(wh, xh);
            *(u32*)(sm + OP_BLO + so) = pack_bf16(w.x - wh, w.y - xh);
        }
        __syncthreads();

        #pragma unroll
        for (int kb = 0; kb < 4; kb++) {
            u32 ah0, ah1, ah2, ah3, al0, al1, al2, al3;
            ldsm_x4(smb + OP_AHI + apos + kb * 32, ah0, ah1, ah2, ah3);
            ldsm_x4(smb + OP_ALO + apos + kb * 32, al0, al1, al2, al3);
            #pragma unroll
            for (int nb = 0; nb < 8; nb++) {
                u32 b0, b1, c0r, c1r;
                ldsm_x2(smb + OP_BHI + bpos + nb * (8 * SMSTRIDE) + kb * 32, b0, b1);
                mma16816(acc[nb], ah0, ah1, ah2, ah3, b0, b1);
                mma16816(acc[nb], al0, al1, al2, al3, b0, b1);
                ldsm_x2(smb + OP_BLO + bpos + nb * (8 * SMSTRIDE) + kb * 32, c0r, c1r);
                mma16816(acc[nb], ah0, ah1, ah2, ah3, c0r, c1r);
            }
        }
    }

    // epilogue: bias + store out[i][d]
    const int rA = wid * 16 + (lane >> 2), rB = rA + 8;
    #pragma unroll
    for (int nb = 0; nb < 8; nb++) {
        int col = nb * 8 + (lane & 3) * 2;
        float b0 = bo[d0 + col], b1 = bo[d0 + col + 1];
        *(float2*)&out[(size_t)(i0 + rA) * DIMC + d0 + col] =
            make_float2(acc[nb][0] + b0, acc[nb][1] + b1);
        *(float2*)&out[(size_t)(i0 + rB) * DIMC + d0 + col] =
            make_float2(acc[nb][2] + b0, acc[nb][3] + b1);
    }
}

// ================= launch ======================================================
extern "C" void kernel_launch(void* const* d_in, const int* in_sizes, int n_in,
                              void* d_out, int out_size)
{
    const float* x   = (const float*)d_in[0];
    const float* px  = (const float*)d_in[1];
    const float* Wq  = (const float*)d_in[2];
    const float* Wk  = (const float*)d_in[3];
    const float* Wv  = (const float*)d_in[4];
    const float* Wo  = (const float*)d_in[5];
    const float* bo  = (const float*)d_in[6];
    const float* Wdw = (const float*)d_in[7];
    const float* bdw = (const float*)d_in[8];
    const float* Wp  = (const float*)d_in[9];
    float* out = (float*)d_out;

    qproj_kernel<<<dim3(64, 8), 256>>>(x, px, Wq);
    offset_kernel<<<dim3(8, 8), 128>>>(Wdw, bdw, Wp);
    gridsample_kernel<<<4096, 256>>>(x, px);
    kvproj_mma_kernel<<<dim3(16, 8, 4), 128>>>(Wk, Wv);
    attn_kernel<<<dim3(64, HEADS, 2), 128>>>();
    outproj_mma_kernel<<<dim3(64, 8), 128>>>(Wo, bo, out);
}

// round 7
// speedup vs baseline: 2.4387x; 1.1616x over previous
#include <cuda_runtime.h>
#include <cuda_bf16.h>
#include <math.h>

typedef unsigned int u32;
typedef unsigned long long u64;
typedef unsigned long long ull;

#define N_SEQ 4096
#define M_SEQ 1024
#define DIMC  512
#define INNER 512
#define HEADS 8
#define GROUPS 8

// ---------------- warp-MMA helpers (sm_80-class, no arch-suffix gating) --------
__device__ __forceinline__ u32 smem_u32(const void* p) {
    u32 a;
    asm("{ .reg .u64 t; cvta.to.shared.u64 t, %1; cvt.u32.u64 %0, t; }" : "=r"(a) : "l"(p));
    return a;
}
__device__ __forceinline__ float ex2f(float x) {
    float r; asm("ex2.approx.ftz.f32 %0, %1;" : "=f"(r) : "f"(x)); return r;
}
__device__ __forceinline__ void ldsm_x4(u32 addr, u32& r0, u32& r1, u32& r2, u32& r3) {
    asm volatile("ldmatrix.sync.aligned.m8n8.x4.shared.b16 {%0,%1,%2,%3}, [%4];"
        : "=r"(r0), "=r"(r1), "=r"(r2), "=r"(r3) : "r"(addr));
}
__device__ __forceinline__ void ldsm_x2(u32 addr, u32& r0, u32& r1) {
    asm volatile("ldmatrix.sync.aligned.m8n8.x2.shared.b16 {%0,%1}, [%2];"
        : "=r"(r0), "=r"(r1) : "r"(addr));
}
__device__ __forceinline__ void ldsm_x2_t(u32 addr, u32& r0, u32& r1) {
    asm volatile("ldmatrix.sync.aligned.m8n8.x2.trans.shared.b16 {%0,%1}, [%2];"
        : "=r"(r0), "=r"(r1) : "r"(addr));
}
__device__ __forceinline__ void mma16816(float* c, u32 a0, u32 a1, u32 a2, u32 a3,
                                         u32 b0, u32 b1) {
    asm volatile(
        "mma.sync.aligned.m16n8k16.row.col.f32.bf16.bf16.f32 "
        "{%0,%1,%2,%3}, {%4,%5,%6,%7}, {%8,%9}, {%0,%1,%2,%3};"
        : "+f"(c[0]), "+f"(c[1]), "+f"(c[2]), "+f"(c[3])
        : "r"(a0), "r"(a1), "r"(a2), "r"(a3), "r"(b0), "r"(b1));
}
__device__ __forceinline__ u32 pack_bf16(float a, float b) {
    return ((u32)__bfloat16_as_ushort(__float2bfloat16(b)) << 16) |
           (u32)__bfloat16_as_ushort(__float2bfloat16(a));
}
__device__ __forceinline__ float bfhi(float x) {
    return __bfloat162float(__float2bfloat16(x));
}
__device__ __forceinline__ void cp_async16(u32 s, const void* g) {
    asm volatile("cp.async.cg.shared.global [%0], [%1], 16;" :: "r"(s), "l"(g));
}
#define CP_COMMIT() asm volatile("cp.async.commit_group;" ::: "memory")
#define CP_WAIT(n)  asm volatile("cp.async.wait_group %0;" :: "n"(n) : "memory")

// ---------------- scratch (static device globals) ------------------------------
__device__ float g_qT[N_SEQ * DIMC];                 // q[i][c]
__device__ float g_pos[GROUPS * M_SEQ];
__device__ float g_kvT[2 * M_SEQ * INNER];           // kv[s][t][ch]
__device__ __nv_bfloat16 g_khi[2 * M_SEQ * INNER];   // k hi  [s][t][c]
__device__ __nv_bfloat16 g_klo[2 * M_SEQ * INNER];   // k lo
__device__ __nv_bfloat16 g_vhi[2 * M_SEQ * INNER];   // v hi  [s][t][c]
__device__ __nv_bfloat16 g_vlo[2 * M_SEQ * INNER];   // v lo
__device__ float g_att[2 * N_SEQ * INNER];           // attn out [s][i][c]

#define SMSTRIDE 144          // 72 bf16 per row (pad 8 -> conflict-free ldmatrix)
#define QSCL 0.1803368801111204f   // 0.125 * log2(e)

// ================= Kernel 1: q projection via warp-MMA =========================
// q[i][c] = sum_k Wq[c][k] * src[i][base+k], K=128 in 2 chunks of 64
#define OP_AHI 0
#define OP_ALO 9216
#define OP_BHI 18432
#define OP_BLO 27648

__global__ __launch_bounds__(128) void qproj_mma_kernel(
    const float* __restrict__ x, const float* __restrict__ px,
    const float* __restrict__ Wq)
{
    __shared__ __align__(16) char sm[36864];
    const int i0 = blockIdx.x * 64;
    const int g  = blockIdx.y;
    const int c0 = g * 64;
    const float* src = (g < 4) ? px : x;
    const int   base = (g & 3) * 128;
    const int tid = threadIdx.x;
    const int lane = tid & 31, wid = tid >> 5;
    const u32 smb = smem_u32(sm);

    float acc[8][4];
    #pragma unroll
    for (int nb = 0; nb < 8; nb++)
        #pragma unroll
        for (int u = 0; u < 4; u++) acc[nb][u] = 0.f;

    const u32 apos = (wid * 16 + (lane & 7) + ((lane >> 3) & 1) * 8) * SMSTRIDE
                   + ((lane >> 4) & 1) * 16;
    const u32 bpos = (lane & 7) * SMSTRIDE + ((lane >> 3) & 1) * 16;

    for (int k0 = 0; k0 < 128; k0 += 64) {
        __syncthreads();
        for (int idx = tid; idx < 2048; idx += 128) {
            int r = idx >> 5, c2 = idx & 31;
            float2 a = *(const float2*)&src[(size_t)(i0 + r) * DIMC + base + k0 + 2 * c2];
            float ah = bfhi(a.x), bh = bfhi(a.y);
            u32 so = r * SMSTRIDE + c2 * 4;
            *(u32*)(sm + OP_AHI + so) = pack_bf16(ah, bh);
            *(u32*)(sm + OP_ALO + so) = pack_bf16(a.x - ah, a.y - bh);
            float2 w = *(const float2*)&Wq[(c0 + r) * 128 + k0 + 2 * c2];
            float wh = bfhi(w.x), xh = bfhi(w.y);
            *(u32*)(sm + OP_BHI + so) = pack_bf16(wh, xh);
            *(u32*)(sm + OP_BLO + so) = pack_bf16(w.x - wh, w.y - xh);
        }
        __syncthreads();
        #pragma unroll
        for (int kb = 0; kb < 4; kb++) {
            u32 ah0, ah1, ah2, ah3, al0, al1, al2, al3;
            ldsm_x4(smb + OP_AHI + apos + kb * 32, ah0, ah1, ah2, ah3);
            ldsm_x4(smb + OP_ALO + apos + kb * 32, al0, al1, al2, al3);
            #pragma unroll
            for (int nb = 0; nb < 8; nb++) {
                u32 b0, b1, c0r, c1r;
                ldsm_x2(smb + OP_BHI + bpos + nb * (8 * SMSTRIDE) + kb * 32, b0, b1);
                mma16816(acc[nb], ah0, ah1, ah2, ah3, b0, b1);
                mma16816(acc[nb], al0, al1, al2, al3, b0, b1);
                ldsm_x2(smb + OP_BLO + bpos + nb * (8 * SMSTRIDE) + kb * 32, c0r, c1r);
                mma16816(acc[nb], ah0, ah1, ah2, ah3, c0r, c1r);
            }
        }
    }
    const int rA = wid * 16 + (lane >> 2), rB = rA + 8;
    #pragma unroll
    for (int nb = 0; nb < 8; nb++) {
        int col = nb * 8 + (lane & 3) * 2;
        *(float2*)&g_qT[(size_t)(i0 + rA) * DIMC + c0 + col] =
            make_float2(acc[nb][0], acc[nb][1]);
        *(float2*)&g_qT[(size_t)(i0 + rB) * DIMC + c0 + col] =
            make_float2(acc[nb][2], acc[nb][3]);
    }
}

// ================= Kernel 2: offset network ====================================
__global__ __launch_bounds__(128) void offset_kernel(
    const float* __restrict__ Wdw, const float* __restrict__ bdw,
    const float* __restrict__ Wp)
{
    const int g = blockIdx.y;
    const int t = blockIdx.x * 128 + threadIdx.x;
    const int pbase = 4 * t - 1;
    float s = 0.f;
    for (int c = 0; c < 64; c++) {
        float hv = bdw[c];
        #pragma unroll
        for (int k = 0; k < 6; k++) {
            int p = pbase + k;
            if (p >= 0 && p < N_SEQ) hv += Wdw[c * 6 + k] * g_qT[(size_t)p * DIMC + g * 64 + c];
        }
        hv = 0.5f * hv * (1.f + erff(hv * 0.7071067811865476f));
        s += Wp[c] * hv;
    }
    float off = tanhf(s) * 4.0f;
    float vg  = 2.0f * ((float)t + off) / 1023.0f - 1.0f;
    float pos = ((vg + 1.0f) * (float)N_SEQ - 1.0f) * 0.5f;
    g_pos[g * M_SEQ + t] = pos;
}

// ================= Kernel 3: 1-D bilinear grid sample ==========================
__global__ __launch_bounds__(256) void gridsample_kernel(
    const float* __restrict__ x, const float* __restrict__ px)
{
    const int tid = blockIdx.x * 256 + threadIdx.x;
    const int c    = tid & 63;
    const int unit = tid >> 6;
    const int t  = unit & (M_SEQ - 1);
    const int sg = unit >> 10;
    const int g  = sg & 7;
    const int s  = sg >> 3;
    const float* src = (s == 0) ? px : x;
    const float pos = g_pos[g * M_SEQ + t];
    const float x0 = floorf(pos);
    const float w1 = pos - x0;
    const int p0 = (int)x0;
    const int ch = g * 64 + c;
    float v = 0.f;
    if (p0 >= 0 && p0 < N_SEQ)           v += (1.f - w1) * src[p0 * DIMC + ch];
    if (p0 + 1 >= 0 && p0 + 1 < N_SEQ)   v += w1 * src[(p0 + 1) * DIMC + ch];
    g_kvT[(size_t)(s * M_SEQ + t) * INNER + ch] = v;
}

// ================= Kernel 4: k/v projection via warp-MMA =======================
#define KV_AHI 0
#define KV_ALO 9216
#define KV_BHI 18432
#define KV_BLO 27648

__global__ __launch_bounds__(128) void kvproj_mma_kernel(
    const float* __restrict__ Wk, const float* __restrict__ Wv)
{
    __shared__ __align__(16) char sm[36864];
    const int t0 = blockIdx.x * 64;
    const int g  = blockIdx.y;
    const int s  = blockIdx.z & 1;
    const int which = blockIdx.z >> 1;
    const int c0 = g * 64;
    const float* W = which ? Wv : Wk;
    __nv_bfloat16* ohi = which ? g_vhi : g_khi;
    __nv_bfloat16* olo = which ? g_vlo : g_klo;
    const int tid = threadIdx.x;
    const int lane = tid & 31, wid = tid >> 5;
    const u32 smb = smem_u32(sm);

    for (int idx = tid; idx < 2048; idx += 128) {
        int r = idx >> 5, c2 = idx & 31;
        float2 a = *(const float2*)&g_kvT[(size_t)(s * M_SEQ + t0 + r) * INNER + c0 + 2 * c2];
        float ah = bfhi(a.x), bh = bfhi(a.y);
        u32 so = r * SMSTRIDE + c2 * 4;
        *(u32*)(sm + KV_AHI + so) = pack_bf16(ah, bh);
        *(u32*)(sm + KV_ALO + so) = pack_bf16(a.x - ah, a.y - bh);
        float2 w = *(const float2*)&W[(c0 + r) * 64 + 2 * c2];
        float wh = bfhi(w.x), xh = bfhi(w.y);
        *(u32*)(sm + KV_BHI + so) = pack_bf16(wh, xh);
        *(u32*)(sm + KV_BLO + so) = pack_bf16(w.x - wh, w.y - xh);
    }
    __syncthreads();

    float acc[8][4];
    #pragma unroll
    for (int nb = 0; nb < 8; nb++)
        #pragma unroll
        for (int u = 0; u < 4; u++) acc[nb][u] = 0.f;

    const u32 apos = (wid * 16 + (lane & 7) + ((lane >> 3) & 1) * 8) * SMSTRIDE
                   + ((lane >> 4) & 1) * 16;
    const u32 bpos = (lane & 7) * SMSTRIDE + ((lane >> 3) & 1) * 16;

    #pragma unroll
    for (int kb = 0; kb < 4; kb++) {
        u32 ah0, ah1, ah2, ah3, al0, al1, al2, al3;
        ldsm_x4(smb + KV_AHI + apos + kb * 32, ah0, ah1, ah2, ah3);
        ldsm_x4(smb + KV_ALO + apos + kb * 32, al0, al1, al2, al3);
        #pragma unroll
        for (int nb = 0; nb < 8; nb++) {
            u32 b0, b1, c0r, c1r;
            ldsm_x2(smb + KV_BHI + bpos + nb * (8 * SMSTRIDE) + kb * 32, b0, b1);
            mma16816(acc[nb], ah0, ah1, ah2, ah3, b0, b1);
            mma16816(acc[nb], al0, al1, al2, al3, b0, b1);
            ldsm_x2(smb + KV_BLO + bpos + nb * (8 * SMSTRIDE) + kb * 32, c0r, c1r);
            mma16816(acc[nb], ah0, ah1, ah2, ah3, c0r, c1r);
        }
    }

    const int rA = wid * 16 + (lane >> 2), rB = rA + 8;
    #pragma unroll
    for (int nb = 0; nb < 8; nb++) {
        int col = nb * 8 + (lane & 3) * 2;
        float v0 = acc[nb][0], v1 = acc[nb][1];
        float h0 = bfhi(v0), h1 = bfhi(v1);
        size_t iA = (size_t)(s * M_SEQ + t0 + rA) * INNER + c0 + col;
        *(u32*)&ohi[iA] = pack_bf16(h0, h1);
        *(u32*)&olo[iA] = pack_bf16(v0 - h0, v1 - h1);
        float v2 = acc[nb][2], v3 = acc[nb][3];
        float h2 = bfhi(v2), h3 = bfhi(v3);
        size_t iB = (size_t)(s * M_SEQ + t0 + rB) * INNER + c0 + col;
        *(u32*)&ohi[iB] = pack_bf16(h2, h3);
        *(u32*)&olo[iB] = pack_bf16(v2 - h2, v3 - h3);
    }
}

// ================= Kernel 5: warp-MMA flash attention (cp.async pipeline) ======
// CTA: 128 q-rows, 8 warps x 16 rows, 256 threads. Bc=32, double-buffered K/V.
#define BUFB 18432
#define AKHI 0
#define AKLO 4608
#define AVHI 9216
#define AVLO 13824
#define AQLO 18432      // Q lo staging (pre-loop only; Q hi at 0)

__global__ __launch_bounds__(256) void attn_kernel()
{
    __shared__ __align__(16) char sm[36864];
    const int i0 = blockIdx.x * 128;
    const int h  = blockIdx.y;
    const int s  = blockIdx.z;
    const int tid = threadIdx.x;
    const int lane = tid & 31;
    const int wid = tid >> 5;
    const u32 smb = smem_u32(sm);

    // ---- stage Q (scaled, bf16 split) ----
    {
        const float* qbase = g_qT + (size_t)i0 * DIMC + h * 64;
        for (int idx = tid; idx < 4096; idx += 256) {
            int r = idx >> 5, c2 = idx & 31;
            const float* qp = qbase + (size_t)r * DIMC + 2 * c2;
            float a = qp[0] * QSCL, b = qp[1] * QSCL;
            float ah = bfhi(a), bh = bfhi(b);
            *(u32*)(sm + r * SMSTRIDE + c2 * 4)        = pack_bf16(ah, bh);
            *(u32*)(sm + AQLO + r * SMSTRIDE + c2 * 4) = pack_bf16(a - ah, b - bh);
        }
    }
    __syncthreads();

    u32 qh[4][4], ql[4][4];
    {
        int qrow = wid * 16 + (lane & 7) + ((lane >> 3) & 1) * 8;
        u32 qoff = smb + qrow * SMSTRIDE + ((lane >> 4) & 1) * 16;
        #pragma unroll
        for (int kb = 0; kb < 4; kb++) {
            ldsm_x4(qoff + kb * 32, qh[kb][0], qh[kb][1], qh[kb][2], qh[kb][3]);
            ldsm_x4(qoff + AQLO + kb * 32, ql[kb][0], ql[kb][1], ql[kb][2], ql[kb][3]);
        }
    }
    __syncthreads();   // Q frags in regs; smem free for K/V buffers

    const __nv_bfloat16* khb = g_khi + (size_t)s * M_SEQ * INNER + h * 64;
    const __nv_bfloat16* klb = g_klo + (size_t)s * M_SEQ * INNER + h * 64;
    const __nv_bfloat16* vhb = g_vhi + (size_t)s * M_SEQ * INNER + h * 64;
    const __nv_bfloat16* vlb = g_vlo + (size_t)s * M_SEQ * INNER + h * 64;

    const u32 lpK = (lane & 7) * SMSTRIDE + ((lane >> 3) & 1) * 16;
    const u32 lpV = (lane & 7) * SMSTRIDE + ((lane >> 3) & 1) * (8 * SMSTRIDE);
    const int sr = tid >> 3, sc4 = tid & 7;   // staging row/col (32 rows x 8 x 16B)

    float oacc[8][4];
    #pragma unroll
    for (int nd = 0; nd < 8; nd++)
        #pragma unroll
        for (int u = 0; u < 4; u++) oacc[nd][u] = 0.f;
    float mA = -1e30f, mB = -1e30f, lA = 0.f, lB = 0.f;

    // prologue: issue tile 0 into buffer 0
    {
        size_t go = (size_t)sr * INNER + sc4 * 8;
        u32 so = smb + sr * SMSTRIDE + sc4 * 16;
        cp_async16(so + AKHI, khb + go);
        cp_async16(so + AKLO, klb + go);
        cp_async16(so + AVHI, vhb + go);
        cp_async16(so + AVLO, vlb + go);
        CP_COMMIT();
    }

    for (int t = 0; t < 32; t++) {
        if (t + 1 < 32) {
            size_t go = (size_t)((t + 1) * 32 + sr) * INNER + sc4 * 8;
            u32 so = smb + ((t + 1) & 1) * BUFB + sr * SMSTRIDE + sc4 * 16;
            cp_async16(so + AKHI, khb + go);
            cp_async16(so + AKLO, klb + go);
            cp_async16(so + AVHI, vhb + go);
            cp_async16(so + AVLO, vlb + go);
            CP_COMMIT();
            CP_WAIT(1);
        } else {
            CP_WAIT(0);
        }
        __syncthreads();
        const u32 bb = smb + (t & 1) * BUFB;

        // ---- S = Q K^T (hh + lh + hl), 32 keys ----
        float sacc[4][4];
        #pragma unroll
        for (int nb = 0; nb < 4; nb++)
            #pragma unroll
            for (int u = 0; u < 4; u++) sacc[nb][u] = 0.f;
        #pragma unroll
        for (int kb = 0; kb < 4; kb++) {
            #pragma unroll
            for (int nb = 0; nb < 4; nb++) {
                u32 b0, b1, c0, c1;
                ldsm_x2(bb + AKHI + lpK + nb * (8 * SMSTRIDE) + kb * 32, b0, b1);
                mma16816(sacc[nb], qh[kb][0], qh[kb][1], qh[kb][2], qh[kb][3], b0, b1);
                mma16816(sacc[nb], ql[kb][0], ql[kb][1], ql[kb][2], ql[kb][3], b0, b1);
                ldsm_x2(bb + AKLO + lpK + nb * (8 * SMSTRIDE) + kb * 32, c0, c1);
                mma16816(sacc[nb], qh[kb][0], qh[kb][1], qh[kb][2], qh[kb][3], c0, c1);
            }
        }

        // ---- online softmax (base-2) ----
        float tA = -1e30f, tB = -1e30f;
        #pragma unroll
        for (int nb = 0; nb < 4; nb++) {
            tA = fmaxf(tA, fmaxf(sacc[nb][0], sacc[nb][1]));
            tB = fmaxf(tB, fmaxf(sacc[nb][2], sacc[nb][3]));
        }
        tA = fmaxf(tA, __shfl_xor_sync(0xffffffffu, tA, 1));
        tA = fmaxf(tA, __shfl_xor_sync(0xffffffffu, tA, 2));
        tB = fmaxf(tB, __shfl_xor_sync(0xffffffffu, tB, 1));
        tB = fmaxf(tB, __shfl_xor_sync(0xffffffffu, tB, 2));
        float mAn = fmaxf(mA, tA), mBn = fmaxf(mB, tB);
        float cA = ex2f(mA - mAn), cB = ex2f(mB - mBn);
        mA = mAn; mB = mBn;
        float sA = 0.f, sB = 0.f;
        #pragma unroll
        for (int nb = 0; nb < 4; nb++) {
            sacc[nb][0] = ex2f(sacc[nb][0] - mAn);
            sacc[nb][1] = ex2f(sacc[nb][1] - mAn);
            sacc[nb][2] = ex2f(sacc[nb][2] - mBn);
            sacc[nb][3] = ex2f(sacc[nb][3] - mBn);
            sA += sacc[nb][0] + sacc[nb][1];
            sB += sacc[nb][2] + sacc[nb][3];
        }
        sA += __shfl_xor_sync(0xffffffffu, sA, 1);
        sA += __shfl_xor_sync(0xffffffffu, sA, 2);
        sB += __shfl_xor_sync(0xffffffffu, sB, 1);
        sB += __shfl_xor_sync(0xffffffffu, sB, 2);
        lA = lA * cA + sA;
        lB = lB * cB + sB;
        #pragma unroll
        for (int nd = 0; nd < 8; nd++) {
            oacc[nd][0] *= cA; oacc[nd][1] *= cA;
            oacc[nd][2] *= cB; oacc[nd][3] *= cB;
        }

        // ---- O += P V (ph*vh + pl*vh + ph*vl), 2 k-blocks of 16 keys ----
        #pragma unroll
        for (int kb = 0; kb < 2; kb++) {
            const float* pL = sacc[2 * kb];
            const float* pH = sacc[2 * kb + 1];
            float h00 = bfhi(pL[0]), h01 = bfhi(pL[1]), h02 = bfhi(pL[2]), h03 = bfhi(pL[3]);
            float h10 = bfhi(pH[0]), h11 = bfhi(pH[1]), h12 = bfhi(pH[2]), h13 = bfhi(pH[3]);
            u32 a0 = pack_bf16(h00, h01), a1 = pack_bf16(h02, h03);
            u32 a2 = pack_bf16(h10, h11), a3 = pack_bf16(h12, h13);
            u32 e0 = pack_bf16(pL[0] - h00, pL[1] - h01);
            u32 e1 = pack_bf16(pL[2] - h02, pL[3] - h03);
            u32 e2 = pack_bf16(pH[0] - h10, pH[1] - h11);
            u32 e3 = pack_bf16(pH[2] - h12, pH[3] - h13);
            #pragma unroll
            for (int nd = 0; nd < 8; nd++) {
                u32 b0, b1, c0, c1;
                ldsm_x2_t(bb + AVHI + lpV + kb * (16 * SMSTRIDE) + nd * 16, b0, b1);
                mma16816(oacc[nd], a0, a1, a2, a3, b0, b1);
                mma16816(oacc[nd], e0, e1, e2, e3, b0, b1);
                ldsm_x2_t(bb + AVLO + lpV + kb * (16 * SMSTRIDE) + nd * 16, c0, c1);
                mma16816(oacc[nd], a0, a1, a2, a3, c0, c1);
            }
        }
        __syncthreads();   // buffer consumed; safe for t+2 issue
    }

    // ---- epilogue: normalize, store to g_att[s][i][c] ----
    float invA = 1.f / lA, invB = 1.f / lB;
    const int rA = wid * 16 + (lane >> 2), rB = rA + 8;
    float* oA = g_att + (size_t)s * N_SEQ * INNER + (size_t)(i0 + rA) * INNER + h * 64;
    float* oB = g_att + (size_t)s * N_SEQ * INNER + (size_t)(i0 + rB) * INNER + h * 64;
    #pragma unroll
    for (int nd = 0; nd < 8; nd++) {
        int col = nd * 8 + (lane & 3) * 2;
        *(float2*)&oA[col] = make_float2(oacc[nd][0] * invA, oacc[nd][1] * invA);
        *(float2*)&oB[col] = make_float2(oacc[nd][2] * invB, oacc[nd][3] * invB);
    }
}

// ================= Kernel 6: stream-mean + Wo GEMM (warp-MMA) ==================
__global__ __launch_bounds__(128) void outproj_mma_kernel(
    const float* __restrict__ Wo, const float* __restrict__ bo,
    float* __restrict__ out)
{
    __shared__ __align__(16) char sm[36864];
    const int i0 = blockIdx.x * 64;
    const int d0 = blockIdx.y * 64;
    const int tid = threadIdx.x;
    const int lane = tid & 31, wid = tid >> 5;
    const u32 smb = smem_u32(sm);

    float acc[8][4];
    #pragma unroll
    for (int nb = 0; nb < 8; nb++)
        #pragma unroll
        for (int u = 0; u < 4; u++) acc[nb][u] = 0.f;

    const u32 apos = (wid * 16 + (lane & 7) + ((lane >> 3) & 1) * 8) * SMSTRIDE
                   + ((lane >> 4) & 1) * 16;
    const u32 bpos = (lane & 7) * SMSTRIDE + ((lane >> 3) & 1) * 16;

    for (int k0 = 0; k0 < 512; k0 += 64) {
        __syncthreads();
        for (int idx = tid; idx < 2048; idx += 128) {
            int r = idx >> 5, c2 = idx & 31;
            const float* a0p = &g_att[(size_t)(i0 + r) * INNER + k0 + 2 * c2];
            float2 u0 = *(const float2*)a0p;
            float2 u1 = *(const float2*)(a0p + (size_t)N_SEQ * INNER);
            float ax = 0.5f * (u0.x + u1.x), ay = 0.5f * (u0.y + u1.y);
            float ah = bfhi(ax), bh = bfhi(ay);
            u32 so = r * SMSTRIDE + c2 * 4;
            *(u32*)(sm + OP_AHI + so) = pack_bf16(ah, bh);
            *(u32*)(sm + OP_ALO + so) = pack_bf16(ax - ah, ay - bh);
            float2 w = *(const float2*)&Wo[(d0 + r) * INNER + k0 + 2 * c2];
            float wh = bfhi(w.x), xh = bfhi(w.y);
            *(u32*)(sm + OP_BHI + so) = pack_bf16(wh, xh);
            *(u32*)(sm + OP_BLO + so) = pack_bf16(w.x - wh, w.y - xh);
        }
        __syncthreads();

        #pragma unroll
        for (int kb = 0; kb < 4; kb++) {
            u32 ah0, ah1, ah2, ah3, al0, al1, al2, al3;
            ldsm_x4(smb + OP_AHI + apos + kb * 32, ah0, ah1, ah2, ah3);
            ldsm_x4(smb + OP_ALO + apos + kb * 32, al0, al1, al2, al3);
            #pragma unroll
            for (int nb = 0; nb < 8; nb++) {
                u32 b0, b1, c0r, c1r;
                ldsm_x2(smb + OP_BHI + bpos + nb * (8 * SMSTRIDE) + kb * 32, b0, b1);
                mma16816(acc[nb], ah0, ah1, ah2, ah3, b0, b1);
                mma16816(acc[nb], al0, al1, al2, al3, b0, b1);
                ldsm_x2(smb + OP_BLO + bpos + nb * (8 * SMSTRIDE) + kb * 32, c0r, c1r);
                mma16816(acc[nb], ah0, ah1, ah2, ah3, c0r, c1r);
            }
        }
    }

    const int rA = wid * 16 + (lane >> 2), rB = rA + 8;
    #pragma unroll
    for (int nb = 0; nb < 8; nb++) {
        int col = nb * 8 + (lane & 3) * 2;
        float b0 = bo[d0 + col], b1 = bo[d0 + col + 1];
        *(float2*)&out[(size_t)(i0 + rA) * DIMC + d0 + col] =
            make_float2(acc[nb][0] + b0, acc[nb][1] + b1);
        *(float2*)&out[(size_t)(i0 + rB) * DIMC + d0 + col] =
            make_float2(acc[nb][2] + b0, acc[nb][3] + b1);
    }
}

// ================= launch ======================================================
extern "C" void kernel_launch(void* const* d_in, const int* in_sizes, int n_in,
                              void* d_out, int out_size)
{
    const float* x   = (const float*)d_in[0];
    const float* px  = (const float*)d_in[1];
    const float* Wq  = (const float*)d_in[2];
    const float* Wk  = (const float*)d_in[3];
    const float* Wv  = (const float*)d_in[4];
    const float* Wo  = (const float*)d_in[5];
    const float* bo  = (const float*)d_in[6];
    const float* Wdw = (const float*)d_in[7];
    const float* bdw = (const float*)d_in[8];
    const float* Wp  = (const float*)d_in[9];
    float* out = (float*)d_out;

    qproj_mma_kernel<<<dim3(64, 8), 128>>>(x, px, Wq);
    offset_kernel<<<dim3(8, 8), 128>>>(Wdw, bdw, Wp);
    gridsample_kernel<<<4096, 256>>>(x, px);
    kvproj_mma_kernel<<<dim3(16, 8, 4), 128>>>(Wk, Wv);
    attn_kernel<<<dim3(32, HEADS, 2), 256>>>();
    outproj_mma_kernel<<<dim3(64, 8), 128>>>(Wo, bo, out);
}